// round 8
// baseline (speedup 1.0000x reference)
#include <cuda_runtime.h>
#include <cuda_bf16.h>
#include <math.h>

// ---------------------------------------------------------------------------
// MultiHeadAttention via bf16 split-precision tensor cores (mma.sync m16n8k16).
// x = hi + lo (bf16 pair); each GEMM computes hi*hi + lo*hi + hi*lo (fp32 acc).
// Round 8: round-3 proven structure (NO cp.async — suspect in container
// failures) + Q-fragment hoisting + grid.z-fused launches.
// ---------------------------------------------------------------------------

#define S_LEN  4096
#define DMODEL 1024
#define NHEAD  16
#define DK     64

typedef __nv_bfloat16  bf16;
typedef __nv_bfloat162 bf162;

#define SDe ((size_t)S_LEN * DMODEL)    // 4194304
#define DDe ((size_t)DMODEL * DMODEL)   // 1048576

// 6*SD + 8*DD + 8*SD = 67108864 elements = 128 MB scratch
__device__ bf16 g_buf[67108864];

// ---------------------------------------------------------------------------
__device__ __forceinline__ unsigned saddr(const void* p) {
    return (unsigned)__cvta_generic_to_shared(p);
}

#define LDSM4(R, A)                                                            \
    asm volatile("ldmatrix.sync.aligned.m8n8.x4.shared.b16 {%0,%1,%2,%3}, [%4];" \
                 : "=r"((R)[0]), "=r"((R)[1]), "=r"((R)[2]), "=r"((R)[3])      \
                 : "r"(A))
#define LDSM4T(R, A)                                                           \
    asm volatile("ldmatrix.sync.aligned.m8n8.x4.trans.shared.b16 {%0,%1,%2,%3}, [%4];" \
                 : "=r"((R)[0]), "=r"((R)[1]), "=r"((R)[2]), "=r"((R)[3])      \
                 : "r"(A))
#define MMA_BF16(C, A, B0, B1)                                                 \
    asm volatile("mma.sync.aligned.m16n8k16.row.col.f32.bf16.bf16.f32 "        \
                 "{%0,%1,%2,%3}, {%4,%5,%6,%7}, {%8,%9}, {%0,%1,%2,%3};"       \
                 : "+f"((C)[0]), "+f"((C)[1]), "+f"((C)[2]), "+f"((C)[3])      \
                 : "r"((A)[0]), "r"((A)[1]), "r"((A)[2]), "r"((A)[3]),         \
                   "r"(B0), "r"(B1))

__device__ __forceinline__ void store_split(bf16* __restrict__ H, bf16* __restrict__ L,
                                            size_t idx, float a, float b)
{
    bf16 ha = __float2bfloat16_rn(a), hb = __float2bfloat16_rn(b);
    *(bf162*)&H[idx] = __halves2bfloat162(ha, hb);
    *(bf162*)&L[idx] = __floats2bfloat162_rn(a - __bfloat162float(ha),
                                             b - __bfloat162float(hb));
}
__device__ __forceinline__ void split_pack(float a, float b, unsigned& hi, unsigned& lo)
{
    bf16 ha = __float2bfloat16_rn(a), hb = __float2bfloat16_rn(b);
    bf162 hh = __halves2bfloat162(ha, hb);
    hi = *reinterpret_cast<unsigned*>(&hh);
    bf162 ll = __floats2bfloat162_rn(a - __bfloat162float(ha),
                                     b - __bfloat162float(hb));
    lo = *reinterpret_cast<unsigned*>(&ll);
}

// ---------------------------------------------------------------------------
// fp32 -> (hi, lo) bf16 split; grid.z selects among up to 4 sources
// ---------------------------------------------------------------------------
__global__ void split_f32_z(const float* __restrict__ s0, const float* __restrict__ s1,
                            const float* __restrict__ s2, const float* __restrict__ s3,
                            bf16* __restrict__ dstBase, size_t pairStride, size_t loOff,
                            int n4)
{
    const int z = blockIdx.z;
    const float* x = (z == 0) ? s0 : (z == 1) ? s1 : (z == 2) ? s2 : s3;
    bf16* h = dstBase + (size_t)z * pairStride;
    bf16* l = h + loOff;
    int idx = blockIdx.x * blockDim.x + threadIdx.x;
    if (idx >= n4) return;
    float4 v = ((const float4*)x)[idx];
    bf16 h0 = __float2bfloat16_rn(v.x), h1 = __float2bfloat16_rn(v.y);
    bf16 h2 = __float2bfloat16_rn(v.z), h3 = __float2bfloat16_rn(v.w);
    bf162* H = (bf162*)h;
    bf162* L = (bf162*)l;
    H[2 * idx]     = __halves2bfloat162(h0, h1);
    H[2 * idx + 1] = __halves2bfloat162(h2, h3);
    L[2 * idx]     = __floats2bfloat162_rn(v.x - __bfloat162float(h0),
                                           v.y - __bfloat162float(h1));
    L[2 * idx + 1] = __floats2bfloat162_rn(v.z - __bfloat162float(h2),
                                           v.w - __bfloat162float(h3));
}

// ---------------------------------------------------------------------------
// Split-bf16 GEMM (round-3 structure: reg double-buffer, synchronous LDG/STS).
// grid.z selects (A, W, bias, out).  C[M,N] = A[M,K] * W[N,K]^T + bias.
// 128x128 block, BK=16, 8 warps. smem: 2 buffers x 4 arrays x 128x24 = 49152 B
// ---------------------------------------------------------------------------
#define GP 24

__global__ __launch_bounds__(256, 2)
void gemm_bf16_split(const bf16* __restrict__ Abase, const bf16* __restrict__ Wbase,
                     const float* __restrict__ b0, const float* __restrict__ b1,
                     const float* __restrict__ b2,
                     float* __restrict__ Cf, bf16* __restrict__ Obase,
                     int M, int N, int K)
{
    extern __shared__ bf16 smg[];
    const int z = blockIdx.z;
    const bf16* Ah = Abase + (size_t)z * 2 * SDe;
    const bf16* Al = Ah + SDe;
    const bf16* Bh = Wbase + (size_t)z * 2 * DDe;
    const bf16* Bl = Bh + DDe;
    const float* bias = (z == 0) ? b0 : (z == 1) ? b1 : b2;
    bf16* Coh = Obase + (size_t)z * 2 * SDe;
    bf16* Col = Coh + SDe;

    const int tid  = threadIdx.x;
    const int lane = tid & 31, wid = tid >> 5;
    const int g = lane >> 2, t = lane & 3;
    const int li = lane >> 3, lj = lane & 7;
    const int wm0 = (wid & 3) * 32;
    const int wn0 = (wid >> 2) * 64;
    const int rowBase = blockIdx.y * 128, colBase = blockIdx.x * 128;

    float acc[2][8][4];
    #pragma unroll
    for (int a = 0; a < 2; a++)
        #pragma unroll
        for (int b = 0; b < 8; b++)
            #pragma unroll
            for (int c = 0; c < 4; c++) acc[a][b][c] = 0.f;

    const int lrow = tid >> 1, lhalf = (tid & 1) * 8;
    const bf16* pAh = Ah + (size_t)(rowBase + lrow) * K + lhalf;
    const bf16* pAl = Al + (size_t)(rowBase + lrow) * K + lhalf;
    const bf16* pBh = Bh + (size_t)(colBase + lrow) * K + lhalf;
    const bf16* pBl = Bl + (size_t)(colBase + lrow) * K + lhalf;
    const int sts = lrow * GP + lhalf;

    uint4 rAh = *(const uint4*)pAh;
    uint4 rAl = *(const uint4*)pAl;
    uint4 rBh = *(const uint4*)pBh;
    uint4 rBl = *(const uint4*)pBl;
    *(uint4*)&smg[0 * 3072 + sts] = rAh;
    *(uint4*)&smg[1 * 3072 + sts] = rAl;
    *(uint4*)&smg[2 * 3072 + sts] = rBh;
    *(uint4*)&smg[3 * 3072 + sts] = rBl;
    __syncthreads();

    const int KS = K >> 4;
    for (int ks = 0; ks < KS; ks++) {
        const int cur = (ks & 1) * 12288;
        const bool hasNext = (ks + 1 < KS);
        if (hasNext) {
            const int k0 = (ks + 1) << 4;
            rAh = *(const uint4*)(pAh + k0);
            rAl = *(const uint4*)(pAl + k0);
            rBh = *(const uint4*)(pBh + k0);
            rBl = *(const uint4*)(pBl + k0);
        }
        unsigned afh[2][4], afl[2][4];
        #pragma unroll
        for (int mt = 0; mt < 2; mt++) {
            const int row = wm0 + mt * 16 + (li & 1) * 8 + lj;
            const int col = (li >> 1) * 8;
            LDSM4(afh[mt], saddr(&smg[cur + 0 * 3072 + row * GP + col]));
            LDSM4(afl[mt], saddr(&smg[cur + 1 * 3072 + row * GP + col]));
        }
        #pragma unroll
        for (int ntp = 0; ntp < 4; ntp++) {
            const int row = wn0 + ntp * 16 + (li >> 1) * 8 + lj;
            const int col = (li & 1) * 8;
            unsigned bh[4], bl[4];
            LDSM4(bh, saddr(&smg[cur + 2 * 3072 + row * GP + col]));
            LDSM4(bl, saddr(&smg[cur + 3 * 3072 + row * GP + col]));
            #pragma unroll
            for (int mt = 0; mt < 2; mt++) {
                MMA_BF16(acc[mt][2 * ntp],     afh[mt], bh[0], bh[1]);
                MMA_BF16(acc[mt][2 * ntp],     afl[mt], bh[0], bh[1]);
                MMA_BF16(acc[mt][2 * ntp],     afh[mt], bl[0], bl[1]);
                MMA_BF16(acc[mt][2 * ntp + 1], afh[mt], bh[2], bh[3]);
                MMA_BF16(acc[mt][2 * ntp + 1], afl[mt], bh[2], bh[3]);
                MMA_BF16(acc[mt][2 * ntp + 1], afh[mt], bl[2], bl[3]);
            }
        }
        if (hasNext) {
            const int nxt = ((ks + 1) & 1) * 12288;
            *(uint4*)&smg[nxt + 0 * 3072 + sts] = rAh;
            *(uint4*)&smg[nxt + 1 * 3072 + sts] = rAl;
            *(uint4*)&smg[nxt + 2 * 3072 + sts] = rBh;
            *(uint4*)&smg[nxt + 3 * 3072 + sts] = rBl;
        }
        __syncthreads();
    }

    // epilogue
    #pragma unroll
    for (int mt = 0; mt < 2; mt++) {
        const int r0 = rowBase + wm0 + mt * 16 + g;
        #pragma unroll
        for (int nt = 0; nt < 8; nt++) {
            const int c = colBase + wn0 + nt * 8 + 2 * t;
            const float bb0 = bias[c], bb1 = bias[c + 1];
            const float v00 = acc[mt][nt][0] + bb0, v01 = acc[mt][nt][1] + bb1;
            const float v10 = acc[mt][nt][2] + bb0, v11 = acc[mt][nt][3] + bb1;
            const size_t i0 = (size_t)r0 * N + c;
            const size_t i1 = (size_t)(r0 + 8) * N + c;
            if (Cf) {
                *(float2*)&Cf[i0] = make_float2(v00, v01);
                *(float2*)&Cf[i1] = make_float2(v10, v11);
            } else {
                store_split(Coh, Col, i0, v00, v01);
                store_split(Coh, Col, i1, v10, v11);
            }
        }
    }
}

// ---------------------------------------------------------------------------
// Split-bf16 flash attention (round-3 staging: synchronous LDG/STS, single
// K/V buffer, 2 barriers per tile) + Q fragments hoisted to registers.
// Br=128, Bc=64, 8 warps. smem: Q(hi/lo) 128x72 + K,V(hi/lo) 64x72 = 73728 B
// ---------------------------------------------------------------------------
#define AP 72

__global__ __launch_bounds__(256, 2)
void attn_bf16_split(const bf16* __restrict__ Qh, const bf16* __restrict__ Ql,
                     const bf16* __restrict__ Kh, const bf16* __restrict__ Kl,
                     const bf16* __restrict__ Vh, const bf16* __restrict__ Vl,
                     bf16* __restrict__ Ch, bf16* __restrict__ Cl)
{
    extern __shared__ bf16 sma[];
    bf16* QHs = sma;            // 128*72 = 9216
    bf16* QLs = sma + 9216;
    bf16* KHs = sma + 18432;    // 64*72 = 4608
    bf16* KLs = sma + 23040;
    bf16* VHs = sma + 27648;
    bf16* VLs = sma + 32256;

    const int tid = threadIdx.x, lane = tid & 31, wid = tid >> 5;
    const int g = lane >> 2, t = lane & 3;
    const int li = lane >> 3, lj = lane & 7;
    const int h = blockIdx.y;
    const int qBase = blockIdx.x * 128;
    const int hoff = h * DK;
    const int m0 = wid * 16;

    // stage Q tile (hi/lo) — once
    #pragma unroll
    for (int p = 0; p < 4; p++) {
        const int c = tid + p * 256;
        const int r = c >> 3, off = (c & 7) * 8;
        const size_t gi = (size_t)(qBase + r) * DMODEL + hoff + off;
        *(uint4*)&QHs[r * AP + off] = *(const uint4*)&Qh[gi];
        *(uint4*)&QLs[r * AP + off] = *(const uint4*)&Ql[gi];
    }
    __syncthreads();

    // hoist Q fragments to registers (loop-invariant)
    unsigned qfh[4][4], qfl[4][4];
    {
        const int qrow = m0 + (li & 1) * 8 + lj;
        #pragma unroll
        for (int kk = 0; kk < 4; kk++) {
            const int qcol = kk * 16 + (li >> 1) * 8;
            LDSM4(qfh[kk], saddr(&QHs[qrow * AP + qcol]));
            LDSM4(qfl[kk], saddr(&QLs[qrow * AP + qcol]));
        }
    }

    float Oa[8][4];
    #pragma unroll
    for (int a = 0; a < 8; a++)
        #pragma unroll
        for (int b = 0; b < 4; b++) Oa[a][b] = 0.f;
    float mrow0 = -1e30f, mrow1 = -1e30f, lrow0 = 0.f, lrow1 = 0.f;
    const float C1 = 0.125f;  // 1/sqrt(DK)

    for (int c0 = 0; c0 < S_LEN; c0 += 64) {
        __syncthreads();   // previous PV GEMM reads done before overwriting K/V
        #pragma unroll
        for (int p = 0; p < 2; p++) {
            const int c = tid + p * 256;
            const int r = c >> 3, off = (c & 7) * 8;
            const size_t gi = (size_t)(c0 + r) * DMODEL + hoff + off;
            *(uint4*)&KHs[r * AP + off] = *(const uint4*)&Kh[gi];
            *(uint4*)&KLs[r * AP + off] = *(const uint4*)&Kl[gi];
            *(uint4*)&VHs[r * AP + off] = *(const uint4*)&Vh[gi];
            *(uint4*)&VLs[r * AP + off] = *(const uint4*)&Vl[gi];
        }
        __syncthreads();

        // ---- S = Q K^T ----
        float SP[8][4];
        #pragma unroll
        for (int a = 0; a < 8; a++)
            #pragma unroll
            for (int b = 0; b < 4; b++) SP[a][b] = 0.f;

        #pragma unroll
        for (int kk = 0; kk < 4; kk++) {
            #pragma unroll
            for (int ntp = 0; ntp < 4; ntp++) {
                const int krow = ntp * 16 + (li >> 1) * 8 + lj;
                const int kcol = kk * 16 + (li & 1) * 8;
                unsigned bh[4], bl[4];
                LDSM4(bh, saddr(&KHs[krow * AP + kcol]));
                LDSM4(bl, saddr(&KLs[krow * AP + kcol]));
                MMA_BF16(SP[2 * ntp],     qfh[kk], bh[0], bh[1]);
                MMA_BF16(SP[2 * ntp],     qfl[kk], bh[0], bh[1]);
                MMA_BF16(SP[2 * ntp],     qfh[kk], bl[0], bl[1]);
                MMA_BF16(SP[2 * ntp + 1], qfh[kk], bh[2], bh[3]);
                MMA_BF16(SP[2 * ntp + 1], qfl[kk], bh[2], bh[3]);
                MMA_BF16(SP[2 * ntp + 1], qfh[kk], bl[2], bl[3]);
            }
        }

        // ---- online softmax (rows g and g+8) ----
        float mx0 = -1e30f, mx1 = -1e30f;
        #pragma unroll
        for (int nt = 0; nt < 8; nt++) {
            mx0 = fmaxf(mx0, fmaxf(SP[nt][0], SP[nt][1]));
            mx1 = fmaxf(mx1, fmaxf(SP[nt][2], SP[nt][3]));
        }
        mx0 = fmaxf(mx0, __shfl_xor_sync(0xffffffffu, mx0, 1));
        mx0 = fmaxf(mx0, __shfl_xor_sync(0xffffffffu, mx0, 2));
        mx1 = fmaxf(mx1, __shfl_xor_sync(0xffffffffu, mx1, 1));
        mx1 = fmaxf(mx1, __shfl_xor_sync(0xffffffffu, mx1, 2));

        const float mn0 = fmaxf(mrow0, mx0 * C1);
        const float mn1 = fmaxf(mrow1, mx1 * C1);
        const float cor0 = __expf(mrow0 - mn0);
        const float cor1 = __expf(mrow1 - mn1);
        mrow0 = mn0; mrow1 = mn1;

        float rs0 = 0.f, rs1 = 0.f;
        #pragma unroll
        for (int nt = 0; nt < 8; nt++) {
            SP[nt][0] = __expf(fmaf(SP[nt][0], C1, -mn0)); rs0 += SP[nt][0];
            SP[nt][1] = __expf(fmaf(SP[nt][1], C1, -mn0)); rs0 += SP[nt][1];
            SP[nt][2] = __expf(fmaf(SP[nt][2], C1, -mn1)); rs1 += SP[nt][2];
            SP[nt][3] = __expf(fmaf(SP[nt][3], C1, -mn1)); rs1 += SP[nt][3];
        }
        rs0 += __shfl_xor_sync(0xffffffffu, rs0, 1);
        rs0 += __shfl_xor_sync(0xffffffffu, rs0, 2);
        rs1 += __shfl_xor_sync(0xffffffffu, rs1, 1);
        rs1 += __shfl_xor_sync(0xffffffffu, rs1, 2);
        lrow0 = lrow0 * cor0 + rs0;
        lrow1 = lrow1 * cor1 + rs1;
        #pragma unroll
        for (int nt = 0; nt < 8; nt++) {
            Oa[nt][0] *= cor0; Oa[nt][1] *= cor0;
            Oa[nt][2] *= cor1; Oa[nt][3] *= cor1;
        }

        // ---- O += P V ----
        #pragma unroll
        for (int kk = 0; kk < 4; kk++) {
            unsigned aph[4], apl[4];
            split_pack(SP[2 * kk][0],     SP[2 * kk][1],     aph[0], apl[0]);
            split_pack(SP[2 * kk][2],     SP[2 * kk][3],     aph[1], apl[1]);
            split_pack(SP[2 * kk + 1][0], SP[2 * kk + 1][1], aph[2], apl[2]);
            split_pack(SP[2 * kk + 1][2], SP[2 * kk + 1][3], aph[3], apl[3]);
            #pragma unroll
            for (int ntp = 0; ntp < 4; ntp++) {
                const int vrow = kk * 16 + (li & 1) * 8 + lj;
                const int vcol = ntp * 16 + (li >> 1) * 8;
                unsigned bh[4], bl[4];
                LDSM4T(bh, saddr(&VHs[vrow * AP + vcol]));
                LDSM4T(bl, saddr(&VLs[vrow * AP + vcol]));
                MMA_BF16(Oa[2 * ntp],     aph, bh[0], bh[1]);
                MMA_BF16(Oa[2 * ntp],     apl, bh[0], bh[1]);
                MMA_BF16(Oa[2 * ntp],     aph, bl[0], bl[1]);
                MMA_BF16(Oa[2 * ntp + 1], aph, bh[2], bh[3]);
                MMA_BF16(Oa[2 * ntp + 1], apl, bh[2], bh[3]);
                MMA_BF16(Oa[2 * ntp + 1], aph, bl[2], bl[3]);
            }
        }
    }

    // ---- epilogue ----
    const float il0 = 1.f / lrow0;
    const float il1 = 1.f / lrow1;
    const int r0 = qBase + m0 + g;
    #pragma unroll
    for (int nt = 0; nt < 8; nt++) {
        const int c = hoff + nt * 8 + 2 * t;
        store_split(Ch, Cl, (size_t)r0 * DMODEL + c,       Oa[nt][0] * il0, Oa[nt][1] * il0);
        store_split(Ch, Cl, (size_t)(r0 + 8) * DMODEL + c, Oa[nt][2] * il1, Oa[nt][3] * il1);
    }
}

// ---------------------------------------------------------------------------
extern "C" void kernel_launch(void* const* d_in, const int* in_sizes, int n_in,
                              void* d_out, int out_size)
{
    const float* q  = (const float*)d_in[0];
    const float* k  = (const float*)d_in[1];
    const float* v  = (const float*)d_in[2];
    const float* Wq = (const float*)d_in[3];
    const float* bq = (const float*)d_in[4];
    const float* Wk = (const float*)d_in[5];
    const float* bk = (const float*)d_in[6];
    const float* Wv = (const float*)d_in[7];
    const float* bv = (const float*)d_in[8];
    const float* Wo = (const float*)d_in[9];
    const float* bo = (const float*)d_in[10];
    float* out = (float*)d_out;

    bf16* B;
    cudaGetSymbolAddress((void**)&B, g_buf);
    bf16* IN0 = B;                       // 6*SD: (hi,lo) x (q,k,v)
    bf16* W0  = B + 6 * SDe;             // 8*DD: (hi,lo) x (Wq,Wk,Wv,Wo)
    bf16* P0  = W0 + 8 * DDe;            // 8*SD: (hi,lo) x (Q,K,V,Ctx)
    bf16 *Qh = P0,            *Ql = P0 + SDe;
    bf16 *Kh = P0 + 2 * SDe,  *Kl = P0 + 3 * SDe;
    bf16 *Vh = P0 + 4 * SDe,  *Vl = P0 + 5 * SDe;
    bf16 *Cph = P0 + 6 * SDe, *Cpl = P0 + 7 * SDe;
    bf16 *woh = W0 + 6 * DDe;

    cudaFuncSetAttribute(gemm_bf16_split, cudaFuncAttributeMaxDynamicSharedMemorySize, 49152);
    cudaFuncSetAttribute(attn_bf16_split, cudaFuncAttributeMaxDynamicSharedMemorySize, 73728);

    const int T = 256;
    // split inputs q,k,v and weights Wq,Wk,Wv,Wo (fused over grid.z)
    dim3 gsI((unsigned)(SDe / 4 / T), 1, 3);
    split_f32_z<<<gsI, T>>>(q, k, v, nullptr, IN0, 2 * SDe, SDe, (int)(SDe / 4));
    dim3 gsW((unsigned)(DDe / 4 / T), 1, 4);
    split_f32_z<<<gsW, T>>>(Wq, Wk, Wv, Wo, W0, 2 * DDe, DDe, (int)(DDe / 4));

    // fused QKV projections
    dim3 gg(DMODEL / 128, S_LEN / 128, 3);
    gemm_bf16_split<<<gg, 256, 49152>>>(IN0, W0, bq, bk, bv, nullptr, P0,
                                        S_LEN, DMODEL, DMODEL);

    // attention
    dim3 ga(S_LEN / 128, NHEAD, 1);
    attn_bf16_split<<<ga, 256, 73728>>>(Qh, Ql, Kh, Kl, Vh, Vl, Cph, Cpl);

    // output projection (fp32 out)
    dim3 go(DMODEL / 128, S_LEN / 128, 1);
    gemm_bf16_split<<<go, 256, 49152>>>(Cph, woh, bo, bo, bo, out, Cph,
                                        S_LEN, DMODEL, DMODEL);
}

// round 12
// speedup vs baseline: 2.0164x; 2.0164x over previous
#include <cuda_runtime.h>
#include <cuda_fp16.h>
#include <math.h>

// ---------------------------------------------------------------------------
// MultiHeadAttention via fp16 tensor cores (mma.sync m16n8k16.f16, fp32 acc).
// Precision plan (threshold 1e-3, error propagation per-path):
//   Q/K proj + QK^T : single fp16 (errors land in softmax exponent, ~2e-4 out)
//   V proj, PV, out : 3-term fp16 split (hi*hi + lo*hi + hi*lo, ~1e-6)
// No tcgen05 (harness PTX target is compute_103 — arch-conditional ops barred),
// no cp.async (implicated in container failures). Synchronous staging as r3/r8.
// ---------------------------------------------------------------------------

#define S_LEN  4096
#define DMODEL 1024
#define NHEAD  16
#define DK     64

typedef __half  h16;
typedef __half2 h162;

#define SDe ((size_t)S_LEN * DMODEL)    // 4194304
#define DDe ((size_t)DMODEL * DMODEL)   // 1048576

__device__ h16 g_buf[67108864];         // 128 MB scratch (10*SD + 6*DD used)

// ---------------------------------------------------------------------------
__device__ __forceinline__ unsigned saddr(const void* p) {
    return (unsigned)__cvta_generic_to_shared(p);
}

#define LDSM4(R, A)                                                            \
    asm volatile("ldmatrix.sync.aligned.m8n8.x4.shared.b16 {%0,%1,%2,%3}, [%4];" \
                 : "=r"((R)[0]), "=r"((R)[1]), "=r"((R)[2]), "=r"((R)[3])      \
                 : "r"(A))
#define LDSM4T(R, A)                                                           \
    asm volatile("ldmatrix.sync.aligned.m8n8.x4.trans.shared.b16 {%0,%1,%2,%3}, [%4];" \
                 : "=r"((R)[0]), "=r"((R)[1]), "=r"((R)[2]), "=r"((R)[3])      \
                 : "r"(A))
#define MMA_F16(C, A, B0, B1)                                                  \
    asm volatile("mma.sync.aligned.m16n8k16.row.col.f32.f16.f16.f32 "          \
                 "{%0,%1,%2,%3}, {%4,%5,%6,%7}, {%8,%9}, {%0,%1,%2,%3};"       \
                 : "+f"((C)[0]), "+f"((C)[1]), "+f"((C)[2]), "+f"((C)[3])      \
                 : "r"((A)[0]), "r"((A)[1]), "r"((A)[2]), "r"((A)[3]),         \
                   "r"(B0), "r"(B1))

__device__ __forceinline__ void store_split_h(h16* __restrict__ H, h16* __restrict__ L,
                                              size_t idx, float a, float b)
{
    h16 ha = __float2half_rn(a), hb = __float2half_rn(b);
    *(h162*)&H[idx] = __halves2half2(ha, hb);
    *(h162*)&L[idx] = __floats2half2_rn(a - __half2float(ha), b - __half2float(hb));
}
__device__ __forceinline__ void split_pack_h(float a, float b, unsigned& hi, unsigned& lo)
{
    h16 ha = __float2half_rn(a), hb = __float2half_rn(b);
    h162 hh = __halves2half2(ha, hb);
    hi = *reinterpret_cast<unsigned*>(&hh);
    h162 ll = __floats2half2_rn(a - __half2float(ha), b - __half2float(hb));
    lo = *reinterpret_cast<unsigned*>(&ll);
}

// ---------------------------------------------------------------------------
// fp32 -> fp16 single, 4 sources via grid.z
// ---------------------------------------------------------------------------
__global__ void cvt_single_z(const float* __restrict__ s0, const float* __restrict__ s1,
                             const float* __restrict__ s2, const float* __restrict__ s3,
                             h16* __restrict__ d0, h16* __restrict__ d1,
                             h16* __restrict__ d2, h16* __restrict__ d3,
                             int n0, int n1, int n2, int n3)
{
    const int z = blockIdx.z;
    const float* x = (z == 0) ? s0 : (z == 1) ? s1 : (z == 2) ? s2 : s3;
    h16* d       = (z == 0) ? d0 : (z == 1) ? d1 : (z == 2) ? d2 : d3;
    const int n4 = (z == 0) ? n0 : (z == 1) ? n1 : (z == 2) ? n2 : n3;
    int idx = blockIdx.x * blockDim.x + threadIdx.x;
    if (idx >= n4) return;
    float4 v = ((const float4*)x)[idx];
    ((h162*)d)[2 * idx]     = __floats2half2_rn(v.x, v.y);
    ((h162*)d)[2 * idx + 1] = __floats2half2_rn(v.z, v.w);
}

// fp32 -> (hi, lo) fp16 split, 3 sources via grid.z
__global__ void cvt_split_z(const float* __restrict__ s0, const float* __restrict__ s1,
                            const float* __restrict__ s2,
                            h16* __restrict__ h0, h16* __restrict__ l0,
                            h16* __restrict__ h1, h16* __restrict__ l1,
                            h16* __restrict__ h2, h16* __restrict__ l2,
                            int n0, int n1, int n2)
{
    const int z = blockIdx.z;
    const float* x = (z == 0) ? s0 : (z == 1) ? s1 : s2;
    h16* h = (z == 0) ? h0 : (z == 1) ? h1 : h2;
    h16* l = (z == 0) ? l0 : (z == 1) ? l1 : l2;
    const int n4 = (z == 0) ? n0 : (z == 1) ? n1 : n2;
    int idx = blockIdx.x * blockDim.x + threadIdx.x;
    if (idx >= n4) return;
    float4 v = ((const float4*)x)[idx];
    h16 a0 = __float2half_rn(v.x), a1 = __float2half_rn(v.y);
    h16 a2 = __float2half_rn(v.z), a3 = __float2half_rn(v.w);
    ((h162*)h)[2 * idx]     = __halves2half2(a0, a1);
    ((h162*)h)[2 * idx + 1] = __halves2half2(a2, a3);
    ((h162*)l)[2 * idx]     = __floats2half2_rn(v.x - __half2float(a0),
                                                v.y - __half2float(a1));
    ((h162*)l)[2 * idx + 1] = __floats2half2_rn(v.z - __half2float(a2),
                                                v.w - __half2float(a3));
}

// ---------------------------------------------------------------------------
// Single-term fp16 GEMM: C[M,N] = A[M,K]*W[N,K]^T + bias, fp16 out.
// grid.z in {0,1} selects (A,W,bias,out). 128x128 tile, BK=16, 8 warps,
// reg double-buffer, synchronous LDG/STS. smem: 2 buf x 2 arr x 128x24 fp16.
// ---------------------------------------------------------------------------
#define GP 24

__global__ __launch_bounds__(256, 2)
void gemm_f16_single(const h16* __restrict__ A0, const h16* __restrict__ A1,
                     const h16* __restrict__ W0, const h16* __restrict__ W1,
                     const float* __restrict__ b0, const float* __restrict__ b1,
                     h16* __restrict__ O0, h16* __restrict__ O1,
                     int M, int N, int K)
{
    extern __shared__ h16 smg[];
    const int z = blockIdx.z;
    const h16* A = z ? A1 : A0;
    const h16* W = z ? W1 : W0;
    const float* bias = z ? b1 : b0;
    h16* O = z ? O1 : O0;

    const int tid  = threadIdx.x;
    const int lane = tid & 31, wid = tid >> 5;
    const int g = lane >> 2, t = lane & 3;
    const int li = lane >> 3, lj = lane & 7;
    const int wm0 = (wid & 3) * 32;
    const int wn0 = (wid >> 2) * 64;
    const int rowBase = blockIdx.y * 128, colBase = blockIdx.x * 128;

    float acc[2][8][4];
    #pragma unroll
    for (int a = 0; a < 2; a++)
        #pragma unroll
        for (int b = 0; b < 8; b++)
            #pragma unroll
            for (int c = 0; c < 4; c++) acc[a][b][c] = 0.f;

    const int lrow = tid >> 1, lhalf = (tid & 1) * 8;
    const h16* pA = A + (size_t)(rowBase + lrow) * K + lhalf;
    const h16* pW = W + (size_t)(colBase + lrow) * K + lhalf;
    const int sts = lrow * GP + lhalf;

    uint4 rA = *(const uint4*)pA;
    uint4 rW = *(const uint4*)pW;
    *(uint4*)&smg[0 * 3072 + sts] = rA;
    *(uint4*)&smg[1 * 3072 + sts] = rW;
    __syncthreads();

    const int KS = K >> 4;
    for (int ks = 0; ks < KS; ks++) {
        const int cur = (ks & 1) * 6144;
        const bool hasNext = (ks + 1 < KS);
        if (hasNext) {
            const int k0 = (ks + 1) << 4;
            rA = *(const uint4*)(pA + k0);
            rW = *(const uint4*)(pW + k0);
        }
        unsigned af[2][4];
        #pragma unroll
        for (int mt = 0; mt < 2; mt++) {
            const int row = wm0 + mt * 16 + (li & 1) * 8 + lj;
            const int col = (li >> 1) * 8;
            LDSM4(af[mt], saddr(&smg[cur + 0 * 3072 + row * GP + col]));
        }
        #pragma unroll
        for (int ntp = 0; ntp < 4; ntp++) {
            const int row = wn0 + ntp * 16 + (li >> 1) * 8 + lj;
            const int col = (li & 1) * 8;
            unsigned bh[4];
            LDSM4(bh, saddr(&smg[cur + 1 * 3072 + row * GP + col]));
            #pragma unroll
            for (int mt = 0; mt < 2; mt++) {
                MMA_F16(acc[mt][2 * ntp],     af[mt], bh[0], bh[1]);
                MMA_F16(acc[mt][2 * ntp + 1], af[mt], bh[2], bh[3]);
            }
        }
        if (hasNext) {
            const int nxt = ((ks + 1) & 1) * 6144;
            *(uint4*)&smg[nxt + 0 * 3072 + sts] = rA;
            *(uint4*)&smg[nxt + 1 * 3072 + sts] = rW;
        }
        __syncthreads();
    }

    #pragma unroll
    for (int mt = 0; mt < 2; mt++) {
        const int r0 = rowBase + wm0 + mt * 16 + g;
        #pragma unroll
        for (int nt = 0; nt < 8; nt++) {
            const int c = colBase + wn0 + nt * 8 + 2 * t;
            const float bb0 = bias[c], bb1 = bias[c + 1];
            *(h162*)&O[(size_t)r0 * N + c] =
                __floats2half2_rn(acc[mt][nt][0] + bb0, acc[mt][nt][1] + bb1);
            *(h162*)&O[(size_t)(r0 + 8) * N + c] =
                __floats2half2_rn(acc[mt][nt][2] + bb0, acc[mt][nt][3] + bb1);
        }
    }
}

// ---------------------------------------------------------------------------
// 3-term split fp16 GEMM: C = A*W^T + bias, A/W as (hi,lo) pairs.
// Output fp32 (Cf != nullptr) or fp16 hi/lo split.
// Same structure as the proven round-3 kernel. smem: 2 x 4 x 128x24 fp16.
// ---------------------------------------------------------------------------
__global__ __launch_bounds__(256, 2)
void gemm_f16_split(const h16* __restrict__ Ah, const h16* __restrict__ Al,
                    const h16* __restrict__ Bh, const h16* __restrict__ Bl,
                    const float* __restrict__ bias,
                    float* __restrict__ Cf,
                    h16* __restrict__ Coh, h16* __restrict__ Col,
                    int M, int N, int K)
{
    extern __shared__ h16 smg[];
    const int tid  = threadIdx.x;
    const int lane = tid & 31, wid = tid >> 5;
    const int g = lane >> 2, t = lane & 3;
    const int li = lane >> 3, lj = lane & 7;
    const int wm0 = (wid & 3) * 32;
    const int wn0 = (wid >> 2) * 64;
    const int rowBase = blockIdx.y * 128, colBase = blockIdx.x * 128;

    float acc[2][8][4];
    #pragma unroll
    for (int a = 0; a < 2; a++)
        #pragma unroll
        for (int b = 0; b < 8; b++)
            #pragma unroll
            for (int c = 0; c < 4; c++) acc[a][b][c] = 0.f;

    const int lrow = tid >> 1, lhalf = (tid & 1) * 8;
    const h16* pAh = Ah + (size_t)(rowBase + lrow) * K + lhalf;
    const h16* pAl = Al + (size_t)(rowBase + lrow) * K + lhalf;
    const h16* pBh = Bh + (size_t)(colBase + lrow) * K + lhalf;
    const h16* pBl = Bl + (size_t)(colBase + lrow) * K + lhalf;
    const int sts = lrow * GP + lhalf;

    uint4 rAh = *(const uint4*)pAh;
    uint4 rAl = *(const uint4*)pAl;
    uint4 rBh = *(const uint4*)pBh;
    uint4 rBl = *(const uint4*)pBl;
    *(uint4*)&smg[0 * 3072 + sts] = rAh;
    *(uint4*)&smg[1 * 3072 + sts] = rAl;
    *(uint4*)&smg[2 * 3072 + sts] = rBh;
    *(uint4*)&smg[3 * 3072 + sts] = rBl;
    __syncthreads();

    const int KS = K >> 4;
    for (int ks = 0; ks < KS; ks++) {
        const int cur = (ks & 1) * 12288;
        const bool hasNext = (ks + 1 < KS);
        if (hasNext) {
            const int k0 = (ks + 1) << 4;
            rAh = *(const uint4*)(pAh + k0);
            rAl = *(const uint4*)(pAl + k0);
            rBh = *(const uint4*)(pBh + k0);
            rBl = *(const uint4*)(pBl + k0);
        }
        unsigned afh[2][4], afl[2][4];
        #pragma unroll
        for (int mt = 0; mt < 2; mt++) {
            const int row = wm0 + mt * 16 + (li & 1) * 8 + lj;
            const int col = (li >> 1) * 8;
            LDSM4(afh[mt], saddr(&smg[cur + 0 * 3072 + row * GP + col]));
            LDSM4(afl[mt], saddr(&smg[cur + 1 * 3072 + row * GP + col]));
        }
        #pragma unroll
        for (int ntp = 0; ntp < 4; ntp++) {
            const int row = wn0 + ntp * 16 + (li >> 1) * 8 + lj;
            const int col = (li & 1) * 8;
            unsigned bh[4], bl[4];
            LDSM4(bh, saddr(&smg[cur + 2 * 3072 + row * GP + col]));
            LDSM4(bl, saddr(&smg[cur + 3 * 3072 + row * GP + col]));
            #pragma unroll
            for (int mt = 0; mt < 2; mt++) {
                MMA_F16(acc[mt][2 * ntp],     afh[mt], bh[0], bh[1]);
                MMA_F16(acc[mt][2 * ntp],     afl[mt], bh[0], bh[1]);
                MMA_F16(acc[mt][2 * ntp],     afh[mt], bl[0], bl[1]);
                MMA_F16(acc[mt][2 * ntp + 1], afh[mt], bh[2], bh[3]);
                MMA_F16(acc[mt][2 * ntp + 1], afl[mt], bh[2], bh[3]);
                MMA_F16(acc[mt][2 * ntp + 1], afh[mt], bl[2], bl[3]);
            }
        }
        if (hasNext) {
            const int nxt = ((ks + 1) & 1) * 12288;
            *(uint4*)&smg[nxt + 0 * 3072 + sts] = rAh;
            *(uint4*)&smg[nxt + 1 * 3072 + sts] = rAl;
            *(uint4*)&smg[nxt + 2 * 3072 + sts] = rBh;
            *(uint4*)&smg[nxt + 3 * 3072 + sts] = rBl;
        }
        __syncthreads();
    }

    #pragma unroll
    for (int mt = 0; mt < 2; mt++) {
        const int r0 = rowBase + wm0 + mt * 16 + g;
        #pragma unroll
        for (int nt = 0; nt < 8; nt++) {
            const int c = colBase + wn0 + nt * 8 + 2 * t;
            const float bb0 = bias[c], bb1 = bias[c + 1];
            const float v00 = acc[mt][nt][0] + bb0, v01 = acc[mt][nt][1] + bb1;
            const float v10 = acc[mt][nt][2] + bb0, v11 = acc[mt][nt][3] + bb1;
            const size_t i0 = (size_t)r0 * N + c;
            const size_t i1 = (size_t)(r0 + 8) * N + c;
            if (Cf) {
                *(float2*)&Cf[i0] = make_float2(v00, v01);
                *(float2*)&Cf[i1] = make_float2(v10, v11);
            } else {
                store_split_h(Coh, Col, i0, v00, v01);
                store_split_h(Coh, Col, i1, v10, v11);
            }
        }
    }
}

// ---------------------------------------------------------------------------
// Flash attention: Q,K single fp16; V fp16 hi/lo; P split fp16 for PV.
// Br=128, Bc=64, 8 warps. smem: Q 128x72 + (K,Vh,Vl) 64x72 = 46080 B.
// Round-3 proven staging: synchronous LDG/STS, 2 barriers/tile, no Q hoist.
// ---------------------------------------------------------------------------
#define AP 72

__global__ __launch_bounds__(256, 2)
void attn_f16(const h16* __restrict__ Qf, const h16* __restrict__ Kf,
              const h16* __restrict__ Vh, const h16* __restrict__ Vl,
              h16* __restrict__ Ch, h16* __restrict__ Cl)
{
    extern __shared__ h16 sma[];
    h16* Qs  = sma;             // 128*72 = 9216
    h16* Ks  = sma + 9216;      // 64*72 = 4608
    h16* VHs = sma + 13824;
    h16* VLs = sma + 18432;

    const int tid = threadIdx.x, lane = tid & 31, wid = tid >> 5;
    const int g = lane >> 2, t = lane & 3;
    const int li = lane >> 3, lj = lane & 7;
    const int h = blockIdx.y;
    const int qBase = blockIdx.x * 128;
    const int hoff = h * DK;
    const int m0 = wid * 16;

    // stage Q tile (single fp16)
    #pragma unroll
    for (int p = 0; p < 4; p++) {
        const int c = tid + p * 256;
        const int r = c >> 3, off = (c & 7) * 8;
        *(uint4*)&Qs[r * AP + off] =
            *(const uint4*)&Qf[(size_t)(qBase + r) * DMODEL + hoff + off];
    }

    float Oa[8][4];
    #pragma unroll
    for (int a = 0; a < 8; a++)
        #pragma unroll
        for (int b = 0; b < 4; b++) Oa[a][b] = 0.f;
    float mrow0 = -1e30f, mrow1 = -1e30f, lrow0 = 0.f, lrow1 = 0.f;
    const float C1 = 0.125f;  // 1/sqrt(DK)

    for (int c0 = 0; c0 < S_LEN; c0 += 64) {
        __syncthreads();
        #pragma unroll
        for (int p = 0; p < 2; p++) {
            const int c = tid + p * 256;
            const int r = c >> 3, off = (c & 7) * 8;
            const size_t gi = (size_t)(c0 + r) * DMODEL + hoff + off;
            *(uint4*)&Ks[r * AP + off]  = *(const uint4*)&Kf[gi];
            *(uint4*)&VHs[r * AP + off] = *(const uint4*)&Vh[gi];
            *(uint4*)&VLs[r * AP + off] = *(const uint4*)&Vl[gi];
        }
        __syncthreads();

        // ---- S = Q K^T (single-term fp16) ----
        float SP[8][4];
        #pragma unroll
        for (int a = 0; a < 8; a++)
            #pragma unroll
            for (int b = 0; b < 4; b++) SP[a][b] = 0.f;

        #pragma unroll
        for (int kk = 0; kk < 4; kk++) {
            unsigned q4[4];
            const int qrow = m0 + (li & 1) * 8 + lj;
            const int qcol = kk * 16 + (li >> 1) * 8;
            LDSM4(q4, saddr(&Qs[qrow * AP + qcol]));
            #pragma unroll
            for (int ntp = 0; ntp < 4; ntp++) {
                const int krow = ntp * 16 + (li >> 1) * 8 + lj;
                const int kcol = kk * 16 + (li & 1) * 8;
                unsigned bh[4];
                LDSM4(bh, saddr(&Ks[krow * AP + kcol]));
                MMA_F16(SP[2 * ntp],     q4, bh[0], bh[1]);
                MMA_F16(SP[2 * ntp + 1], q4, bh[2], bh[3]);
            }
        }

        // ---- online softmax (rows g and g+8) ----
        float mx0 = -1e30f, mx1 = -1e30f;
        #pragma unroll
        for (int nt = 0; nt < 8; nt++) {
            mx0 = fmaxf(mx0, fmaxf(SP[nt][0], SP[nt][1]));
            mx1 = fmaxf(mx1, fmaxf(SP[nt][2], SP[nt][3]));
        }
        mx0 = fmaxf(mx0, __shfl_xor_sync(0xffffffffu, mx0, 1));
        mx0 = fmaxf(mx0, __shfl_xor_sync(0xffffffffu, mx0, 2));
        mx1 = fmaxf(mx1, __shfl_xor_sync(0xffffffffu, mx1, 1));
        mx1 = fmaxf(mx1, __shfl_xor_sync(0xffffffffu, mx1, 2));

        const float mn0 = fmaxf(mrow0, mx0 * C1);
        const float mn1 = fmaxf(mrow1, mx1 * C1);
        const float cor0 = __expf(mrow0 - mn0);
        const float cor1 = __expf(mrow1 - mn1);
        mrow0 = mn0; mrow1 = mn1;

        float rs0 = 0.f, rs1 = 0.f;
        #pragma unroll
        for (int nt = 0; nt < 8; nt++) {
            SP[nt][0] = __expf(fmaf(SP[nt][0], C1, -mn0)); rs0 += SP[nt][0];
            SP[nt][1] = __expf(fmaf(SP[nt][1], C1, -mn0)); rs0 += SP[nt][1];
            SP[nt][2] = __expf(fmaf(SP[nt][2], C1, -mn1)); rs1 += SP[nt][2];
            SP[nt][3] = __expf(fmaf(SP[nt][3], C1, -mn1)); rs1 += SP[nt][3];
        }
        rs0 += __shfl_xor_sync(0xffffffffu, rs0, 1);
        rs0 += __shfl_xor_sync(0xffffffffu, rs0, 2);
        rs1 += __shfl_xor_sync(0xffffffffu, rs1, 1);
        rs1 += __shfl_xor_sync(0xffffffffu, rs1, 2);
        lrow0 = lrow0 * cor0 + rs0;
        lrow1 = lrow1 * cor1 + rs1;
        #pragma unroll
        for (int nt = 0; nt < 8; nt++) {
            Oa[nt][0] *= cor0; Oa[nt][1] *= cor0;
            Oa[nt][2] *= cor1; Oa[nt][3] *= cor1;
        }

        // ---- O += P V (3-term fp16 split) ----
        #pragma unroll
        for (int kk = 0; kk < 4; kk++) {
            unsigned aph[4], apl[4];
            split_pack_h(SP[2 * kk][0],     SP[2 * kk][1],     aph[0], apl[0]);
            split_pack_h(SP[2 * kk][2],     SP[2 * kk][3],     aph[1], apl[1]);
            split_pack_h(SP[2 * kk + 1][0], SP[2 * kk + 1][1], aph[2], apl[2]);
            split_pack_h(SP[2 * kk + 1][2], SP[2 * kk + 1][3], aph[3], apl[3]);
            #pragma unroll
            for (int ntp = 0; ntp < 4; ntp++) {
                const int vrow = kk * 16 + (li & 1) * 8 + lj;
                const int vcol = ntp * 16 + (li >> 1) * 8;
                unsigned bh[4], bl[4];
                LDSM4T(bh, saddr(&VHs[vrow * AP + vcol]));
                LDSM4T(bl, saddr(&VLs[vrow * AP + vcol]));
                MMA_F16(Oa[2 * ntp],     aph, bh[0], bh[1]);
                MMA_F16(Oa[2 * ntp],     apl, bh[0], bh[1]);
                MMA_F16(Oa[2 * ntp],     aph, bl[0], bl[1]);
                MMA_F16(Oa[2 * ntp + 1], aph, bh[2], bh[3]);
                MMA_F16(Oa[2 * ntp + 1], apl, bh[2], bh[3]);
                MMA_F16(Oa[2 * ntp + 1], aph, bl[2], bl[3]);
            }
        }
    }

    // ---- epilogue: normalize, split-store ctx ----
    const float il0 = 1.f / lrow0;
    const float il1 = 1.f / lrow1;
    const int r0 = qBase + m0 + g;
    #pragma unroll
    for (int nt = 0; nt < 8; nt++) {
        const int c = hoff + nt * 8 + 2 * t;
        store_split_h(Ch, Cl, (size_t)r0 * DMODEL + c,       Oa[nt][0] * il0, Oa[nt][1] * il0);
        store_split_h(Ch, Cl, (size_t)(r0 + 8) * DMODEL + c, Oa[nt][2] * il1, Oa[nt][3] * il1);
    }
}

// ---------------------------------------------------------------------------
extern "C" void kernel_launch(void* const* d_in, const int* in_sizes, int n_in,
                              void* d_out, int out_size)
{
    const float* q  = (const float*)d_in[0];
    const float* k  = (const float*)d_in[1];
    const float* v  = (const float*)d_in[2];
    const float* Wq = (const float*)d_in[3];
    const float* bq = (const float*)d_in[4];
    const float* Wk = (const float*)d_in[5];
    const float* bk = (const float*)d_in[6];
    const float* Wv = (const float*)d_in[7];
    const float* bv = (const float*)d_in[8];
    const float* Wo = (const float*)d_in[9];
    const float* bo = (const float*)d_in[10];
    float* out = (float*)d_out;

    h16* B;
    cudaGetSymbolAddress((void**)&B, g_buf);
    // layout (elements): see offsets below; total 10*SD + 6*DD < capacity
    h16* q16  = B;
    h16* k16  = B + SDe;
    h16* Wq16 = B + 2 * SDe;
    h16* Wk16 = B + 2 * SDe + DDe;
    h16* vh   = B + 2 * SDe + 2 * DDe;
    h16* vl   = B + 3 * SDe + 2 * DDe;
    h16* Wvh  = B + 4 * SDe + 2 * DDe;
    h16* Wvl  = B + 4 * SDe + 3 * DDe;
    h16* Woh  = B + 4 * SDe + 4 * DDe;
    h16* Wol  = B + 4 * SDe + 5 * DDe;
    h16* Qf   = B + 4 * SDe + 6 * DDe;
    h16* Kf   = B + 5 * SDe + 6 * DDe;
    h16* Vph  = B + 6 * SDe + 6 * DDe;
    h16* Vpl  = B + 7 * SDe + 6 * DDe;
    h16* Ch   = B + 8 * SDe + 6 * DDe;
    h16* Cl   = B + 9 * SDe + 6 * DDe;

    cudaFuncSetAttribute(gemm_f16_single, cudaFuncAttributeMaxDynamicSharedMemorySize, 24576);
    cudaFuncSetAttribute(gemm_f16_split,  cudaFuncAttributeMaxDynamicSharedMemorySize, 49152);
    cudaFuncSetAttribute(attn_f16,        cudaFuncAttributeMaxDynamicSharedMemorySize, 46080);

    const int T = 256;
    const int nSD4 = (int)(SDe / 4), nDD4 = (int)(DDe / 4);

    // conversions
    dim3 gc1((unsigned)(nSD4 / T), 1, 4);   // q, k, Wq, Wk -> single fp16
    cvt_single_z<<<gc1, T>>>(q, k, Wq, Wk, q16, k16, Wq16, Wk16,
                             nSD4, nSD4, nDD4, nDD4);
    dim3 gc2((unsigned)(nSD4 / T), 1, 3);   // v, Wv, Wo -> split fp16
    cvt_split_z<<<gc2, T>>>(v, Wv, Wo, vh, vl, Wvh, Wvl, Woh, Wol,
                            nSD4, nDD4, nDD4);

    // Q,K projections (single-term), fused over z
    dim3 gg(DMODEL / 128, S_LEN / 128, 2);
    gemm_f16_single<<<gg, 256, 24576>>>(q16, k16, Wq16, Wk16, bq, bk, Qf, Kf,
                                        S_LEN, DMODEL, DMODEL);

    // V projection (3-term split)
    dim3 gv(DMODEL / 128, S_LEN / 128, 1);
    gemm_f16_split<<<gv, 256, 49152>>>(vh, vl, Wvh, Wvl, bv, nullptr, Vph, Vpl,
                                       S_LEN, DMODEL, DMODEL);

    // attention
    dim3 ga(S_LEN / 128, NHEAD, 1);
    attn_f16<<<ga, 256, 46080>>>(Qf, Kf, Vph, Vpl, Ch, Cl);

    // output projection (3-term split, fp32 out)
    gemm_f16_split<<<gv, 256, 49152>>>(Ch, Cl, Woh, Wol, bo, out, nullptr, nullptr,
                                       S_LEN, DMODEL, DMODEL);
}

// round 14
// speedup vs baseline: 2.0652x; 1.0242x over previous
#include <cuda_runtime.h>
#include <cuda_fp16.h>
#include <math.h>

// ---------------------------------------------------------------------------
// MultiHeadAttention via fp16 tensor cores (mma.sync m16n8k16.f16, fp32 acc).
// Precision plan (unchanged from r12, measured rel_err 4.3e-5):
//   Q/K proj + QK^T : single fp16   |   V proj, PV, out proj : 3-term split
// Round 13: attention K/V register-prefetch (r3-GEMM pattern), QKV projections
// fused into one launch. No tcgen05 (compute_103 PTX), no cp.async.
// ---------------------------------------------------------------------------

#define S_LEN  4096
#define DMODEL 1024
#define NHEAD  16
#define DK     64

typedef __half  h16;
typedef __half2 h162;

#define SDe ((size_t)S_LEN * DMODEL)    // 4194304
#define DDe ((size_t)DMODEL * DMODEL)   // 1048576

__device__ h16 g_buf[67108864];         // 128 MB scratch (10*SD + 6*DD used)

// ---------------------------------------------------------------------------
__device__ __forceinline__ unsigned saddr(const void* p) {
    return (unsigned)__cvta_generic_to_shared(p);
}

#define LDSM4(R, A)                                                            \
    asm volatile("ldmatrix.sync.aligned.m8n8.x4.shared.b16 {%0,%1,%2,%3}, [%4];" \
                 : "=r"((R)[0]), "=r"((R)[1]), "=r"((R)[2]), "=r"((R)[3])      \
                 : "r"(A))
#define LDSM4T(R, A)                                                           \
    asm volatile("ldmatrix.sync.aligned.m8n8.x4.trans.shared.b16 {%0,%1,%2,%3}, [%4];" \
                 : "=r"((R)[0]), "=r"((R)[1]), "=r"((R)[2]), "=r"((R)[3])      \
                 : "r"(A))
#define MMA_F16(C, A, B0, B1)                                                  \
    asm volatile("mma.sync.aligned.m16n8k16.row.col.f32.f16.f16.f32 "          \
                 "{%0,%1,%2,%3}, {%4,%5,%6,%7}, {%8,%9}, {%0,%1,%2,%3};"       \
                 : "+f"((C)[0]), "+f"((C)[1]), "+f"((C)[2]), "+f"((C)[3])      \
                 : "r"((A)[0]), "r"((A)[1]), "r"((A)[2]), "r"((A)[3]),         \
                   "r"(B0), "r"(B1))

__device__ __forceinline__ void store_split_h(h16* __restrict__ H, h16* __restrict__ L,
                                              size_t idx, float a, float b)
{
    h16 ha = __float2half_rn(a), hb = __float2half_rn(b);
    *(h162*)&H[idx] = __halves2half2(ha, hb);
    *(h162*)&L[idx] = __floats2half2_rn(a - __half2float(ha), b - __half2float(hb));
}
__device__ __forceinline__ void split_pack_h(float a, float b, unsigned& hi, unsigned& lo)
{
    h16 ha = __float2half_rn(a), hb = __float2half_rn(b);
    h162 hh = __halves2half2(ha, hb);
    hi = *reinterpret_cast<unsigned*>(&hh);
    h162 ll = __floats2half2_rn(a - __half2float(ha), b - __half2float(hb));
    lo = *reinterpret_cast<unsigned*>(&ll);
}

// ---------------------------------------------------------------------------
// conversions (fused over grid.z)
// ---------------------------------------------------------------------------
__global__ void cvt_single_z(const float* __restrict__ s0, const float* __restrict__ s1,
                             const float* __restrict__ s2, const float* __restrict__ s3,
                             h16* __restrict__ d0, h16* __restrict__ d1,
                             h16* __restrict__ d2, h16* __restrict__ d3,
                             int n0, int n1, int n2, int n3)
{
    const int z = blockIdx.z;
    const float* x = (z == 0) ? s0 : (z == 1) ? s1 : (z == 2) ? s2 : s3;
    h16* d       = (z == 0) ? d0 : (z == 1) ? d1 : (z == 2) ? d2 : d3;
    const int n4 = (z == 0) ? n0 : (z == 1) ? n1 : (z == 2) ? n2 : n3;
    int idx = blockIdx.x * blockDim.x + threadIdx.x;
    if (idx >= n4) return;
    float4 v = ((const float4*)x)[idx];
    ((h162*)d)[2 * idx]     = __floats2half2_rn(v.x, v.y);
    ((h162*)d)[2 * idx + 1] = __floats2half2_rn(v.z, v.w);
}

__global__ void cvt_split_z(const float* __restrict__ s0, const float* __restrict__ s1,
                            const float* __restrict__ s2,
                            h16* __restrict__ h0, h16* __restrict__ l0,
                            h16* __restrict__ h1, h16* __restrict__ l1,
                            h16* __restrict__ h2, h16* __restrict__ l2,
                            int n0, int n1, int n2)
{
    const int z = blockIdx.z;
    const float* x = (z == 0) ? s0 : (z == 1) ? s1 : s2;
    h16* h = (z == 0) ? h0 : (z == 1) ? h1 : h2;
    h16* l = (z == 0) ? l0 : (z == 1) ? l1 : l2;
    const int n4 = (z == 0) ? n0 : (z == 1) ? n1 : n2;
    int idx = blockIdx.x * blockDim.x + threadIdx.x;
    if (idx >= n4) return;
    float4 v = ((const float4*)x)[idx];
    h16 a0 = __float2half_rn(v.x), a1 = __float2half_rn(v.y);
    h16 a2 = __float2half_rn(v.z), a3 = __float2half_rn(v.w);
    ((h162*)h)[2 * idx]     = __halves2half2(a0, a1);
    ((h162*)h)[2 * idx + 1] = __halves2half2(a2, a3);
    ((h162*)l)[2 * idx]     = __floats2half2_rn(v.x - __half2float(a0),
                                                v.y - __half2float(a1));
    ((h162*)l)[2 * idx + 1] = __floats2half2_rn(v.z - __half2float(a2),
                                                v.w - __half2float(a3));
}

// ---------------------------------------------------------------------------
// GEMM bodies (device-inline; M=S_LEN, N=K=DMODEL). 128x128 tile, BK=16,
// 8 warps, reg double-buffer, synchronous LDG/STS (proven pattern).
// ---------------------------------------------------------------------------
#define GP 24

__device__ __forceinline__
void gemm_single_body(const h16* __restrict__ A, const h16* __restrict__ W,
                      const float* __restrict__ bias, h16* __restrict__ O,
                      h16* smg)
{
    const int tid  = threadIdx.x;
    const int lane = tid & 31, wid = tid >> 5;
    const int g = lane >> 2, t = lane & 3;
    const int li = lane >> 3, lj = lane & 7;
    const int wm0 = (wid & 3) * 32;
    const int wn0 = (wid >> 2) * 64;
    const int rowBase = blockIdx.y * 128, colBase = blockIdx.x * 128;

    float acc[2][8][4];
    #pragma unroll
    for (int a = 0; a < 2; a++)
        #pragma unroll
        for (int b = 0; b < 8; b++)
            #pragma unroll
            for (int c = 0; c < 4; c++) acc[a][b][c] = 0.f;

    const int lrow = tid >> 1, lhalf = (tid & 1) * 8;
    const h16* pA = A + (size_t)(rowBase + lrow) * DMODEL + lhalf;
    const h16* pW = W + (size_t)(colBase + lrow) * DMODEL + lhalf;
    const int sts = lrow * GP + lhalf;

    uint4 rA = *(const uint4*)pA;
    uint4 rW = *(const uint4*)pW;
    *(uint4*)&smg[0 * 3072 + sts] = rA;
    *(uint4*)&smg[1 * 3072 + sts] = rW;
    __syncthreads();

    const int KS = DMODEL >> 4;
    for (int ks = 0; ks < KS; ks++) {
        const int cur = (ks & 1) * 6144;
        const bool hasNext = (ks + 1 < KS);
        if (hasNext) {
            const int k0 = (ks + 1) << 4;
            rA = *(const uint4*)(pA + k0);
            rW = *(const uint4*)(pW + k0);
        }
        unsigned af[2][4];
        #pragma unroll
        for (int mt = 0; mt < 2; mt++) {
            const int row = wm0 + mt * 16 + (li & 1) * 8 + lj;
            const int col = (li >> 1) * 8;
            LDSM4(af[mt], saddr(&smg[cur + 0 * 3072 + row * GP + col]));
        }
        #pragma unroll
        for (int ntp = 0; ntp < 4; ntp++) {
            const int row = wn0 + ntp * 16 + (li >> 1) * 8 + lj;
            const int col = (li & 1) * 8;
            unsigned bh[4];
            LDSM4(bh, saddr(&smg[cur + 1 * 3072 + row * GP + col]));
            #pragma unroll
            for (int mt = 0; mt < 2; mt++) {
                MMA_F16(acc[mt][2 * ntp],     af[mt], bh[0], bh[1]);
                MMA_F16(acc[mt][2 * ntp + 1], af[mt], bh[2], bh[3]);
            }
        }
        if (hasNext) {
            const int nxt = ((ks + 1) & 1) * 6144;
            *(uint4*)&smg[nxt + 0 * 3072 + sts] = rA;
            *(uint4*)&smg[nxt + 1 * 3072 + sts] = rW;
        }
        __syncthreads();
    }

    #pragma unroll
    for (int mt = 0; mt < 2; mt++) {
        const int r0 = rowBase + wm0 + mt * 16 + g;
        #pragma unroll
        for (int nt = 0; nt < 8; nt++) {
            const int c = colBase + wn0 + nt * 8 + 2 * t;
            const float bb0 = bias[c], bb1 = bias[c + 1];
            *(h162*)&O[(size_t)r0 * DMODEL + c] =
                __floats2half2_rn(acc[mt][nt][0] + bb0, acc[mt][nt][1] + bb1);
            *(h162*)&O[(size_t)(r0 + 8) * DMODEL + c] =
                __floats2half2_rn(acc[mt][nt][2] + bb0, acc[mt][nt][3] + bb1);
        }
    }
}

__device__ __forceinline__
void gemm_split_body(const h16* __restrict__ Ah, const h16* __restrict__ Al,
                     const h16* __restrict__ Bh, const h16* __restrict__ Bl,
                     const float* __restrict__ bias,
                     float* __restrict__ Cf,
                     h16* __restrict__ Coh, h16* __restrict__ Col,
                     h16* smg)
{
    const int tid  = threadIdx.x;
    const int lane = tid & 31, wid = tid >> 5;
    const int g = lane >> 2, t = lane & 3;
    const int li = lane >> 3, lj = lane & 7;
    const int wm0 = (wid & 3) * 32;
    const int wn0 = (wid >> 2) * 64;
    const int rowBase = blockIdx.y * 128, colBase = blockIdx.x * 128;

    float acc[2][8][4];
    #pragma unroll
    for (int a = 0; a < 2; a++)
        #pragma unroll
        for (int b = 0; b < 8; b++)
            #pragma unroll
            for (int c = 0; c < 4; c++) acc[a][b][c] = 0.f;

    const int lrow = tid >> 1, lhalf = (tid & 1) * 8;
    const h16* pAh = Ah + (size_t)(rowBase + lrow) * DMODEL + lhalf;
    const h16* pAl = Al + (size_t)(rowBase + lrow) * DMODEL + lhalf;
    const h16* pBh = Bh + (size_t)(colBase + lrow) * DMODEL + lhalf;
    const h16* pBl = Bl + (size_t)(colBase + lrow) * DMODEL + lhalf;
    const int sts = lrow * GP + lhalf;

    uint4 rAh = *(const uint4*)pAh;
    uint4 rAl = *(const uint4*)pAl;
    uint4 rBh = *(const uint4*)pBh;
    uint4 rBl = *(const uint4*)pBl;
    *(uint4*)&smg[0 * 3072 + sts] = rAh;
    *(uint4*)&smg[1 * 3072 + sts] = rAl;
    *(uint4*)&smg[2 * 3072 + sts] = rBh;
    *(uint4*)&smg[3 * 3072 + sts] = rBl;
    __syncthreads();

    const int KS = DMODEL >> 4;
    for (int ks = 0; ks < KS; ks++) {
        const int cur = (ks & 1) * 12288;
        const bool hasNext = (ks + 1 < KS);
        if (hasNext) {
            const int k0 = (ks + 1) << 4;
            rAh = *(const uint4*)(pAh + k0);
            rAl = *(const uint4*)(pAl + k0);
            rBh = *(const uint4*)(pBh + k0);
            rBl = *(const uint4*)(pBl + k0);
        }
        unsigned afh[2][4], afl[2][4];
        #pragma unroll
        for (int mt = 0; mt < 2; mt++) {
            const int row = wm0 + mt * 16 + (li & 1) * 8 + lj;
            const int col = (li >> 1) * 8;
            LDSM4(afh[mt], saddr(&smg[cur + 0 * 3072 + row * GP + col]));
            LDSM4(afl[mt], saddr(&smg[cur + 1 * 3072 + row * GP + col]));
        }
        #pragma unroll
        for (int ntp = 0; ntp < 4; ntp++) {
            const int row = wn0 + ntp * 16 + (li >> 1) * 8 + lj;
            const int col = (li & 1) * 8;
            unsigned bh[4], bl[4];
            LDSM4(bh, saddr(&smg[cur + 2 * 3072 + row * GP + col]));
            LDSM4(bl, saddr(&smg[cur + 3 * 3072 + row * GP + col]));
            #pragma unroll
            for (int mt = 0; mt < 2; mt++) {
                MMA_F16(acc[mt][2 * ntp],     afh[mt], bh[0], bh[1]);
                MMA_F16(acc[mt][2 * ntp],     afl[mt], bh[0], bh[1]);
                MMA_F16(acc[mt][2 * ntp],     afh[mt], bl[0], bl[1]);
                MMA_F16(acc[mt][2 * ntp + 1], afh[mt], bh[2], bh[3]);
                MMA_F16(acc[mt][2 * ntp + 1], afl[mt], bh[2], bh[3]);
                MMA_F16(acc[mt][2 * ntp + 1], afh[mt], bl[2], bl[3]);
            }
        }
        if (hasNext) {
            const int nxt = ((ks + 1) & 1) * 12288;
            *(uint4*)&smg[nxt + 0 * 3072 + sts] = rAh;
            *(uint4*)&smg[nxt + 1 * 3072 + sts] = rAl;
            *(uint4*)&smg[nxt + 2 * 3072 + sts] = rBh;
            *(uint4*)&smg[nxt + 3 * 3072 + sts] = rBl;
        }
        __syncthreads();
    }

    #pragma unroll
    for (int mt = 0; mt < 2; mt++) {
        const int r0 = rowBase + wm0 + mt * 16 + g;
        #pragma unroll
        for (int nt = 0; nt < 8; nt++) {
            const int c = colBase + wn0 + nt * 8 + 2 * t;
            const float bb0 = bias[c], bb1 = bias[c + 1];
            const float v00 = acc[mt][nt][0] + bb0, v01 = acc[mt][nt][1] + bb1;
            const float v10 = acc[mt][nt][2] + bb0, v11 = acc[mt][nt][3] + bb1;
            const size_t i0 = (size_t)r0 * DMODEL + c;
            const size_t i1 = (size_t)(r0 + 8) * DMODEL + c;
            if (Cf) {
                *(float2*)&Cf[i0] = make_float2(v00, v01);
                *(float2*)&Cf[i1] = make_float2(v10, v11);
            } else {
                store_split_h(Coh, Col, i0, v00, v01);
                store_split_h(Coh, Col, i1, v10, v11);
            }
        }
    }
}

// ---------------------------------------------------------------------------
// Fused QKV projections: z=0 -> Q (single), z=1 -> K (single), z=2 -> V (split)
// ---------------------------------------------------------------------------
__global__ __launch_bounds__(256, 2)
void proj_qkv(const h16* __restrict__ q16, const h16* __restrict__ k16,
              const h16* __restrict__ Wq16, const h16* __restrict__ Wk16,
              const float* __restrict__ bq, const float* __restrict__ bk,
              h16* __restrict__ Qf, h16* __restrict__ Kf,
              const h16* __restrict__ vh, const h16* __restrict__ vl,
              const h16* __restrict__ Wvh, const h16* __restrict__ Wvl,
              const float* __restrict__ bv,
              h16* __restrict__ Vph, h16* __restrict__ Vpl)
{
    extern __shared__ h16 smg[];
    const int z = blockIdx.z;
    if (z == 0)      gemm_single_body(q16, Wq16, bq, Qf, smg);
    else if (z == 1) gemm_single_body(k16, Wk16, bk, Kf, smg);
    else             gemm_split_body(vh, vl, Wvh, Wvl, bv, nullptr, Vph, Vpl, smg);
}

// output projection (3-term split, fp32 out)
__global__ __launch_bounds__(256, 2)
void proj_out(const h16* __restrict__ Ch, const h16* __restrict__ Cl,
              const h16* __restrict__ Woh, const h16* __restrict__ Wol,
              const float* __restrict__ bo, float* __restrict__ out)
{
    extern __shared__ h16 smg[];
    gemm_split_body(Ch, Cl, Woh, Wol, bo, out, nullptr, nullptr, smg);
}

// ---------------------------------------------------------------------------
// Flash attention: Q,K single fp16; V fp16 hi/lo; P split fp16 for PV.
// Br=128, Bc=64, 8 warps. K/V staged via register prefetch (next tile's LDGs
// issued before compute of current tile) — r3-GEMM proven pattern.
// smem: Q 128x72 + (K,Vh,Vl) 64x72 = 46080 B.
// ---------------------------------------------------------------------------
#define AP 72

__global__ __launch_bounds__(256, 2)
void attn_f16(const h16* __restrict__ Qf, const h16* __restrict__ Kf,
              const h16* __restrict__ Vh, const h16* __restrict__ Vl,
              h16* __restrict__ Ch, h16* __restrict__ Cl)
{
    extern __shared__ h16 sma[];
    h16* Qs  = sma;             // 128*72 = 9216 el
    h16* Ks  = sma + 9216;      // 64*72 = 4608 el
    h16* VHs = sma + 13824;
    h16* VLs = sma + 18432;

    const int tid = threadIdx.x, lane = tid & 31, wid = tid >> 5;
    const int g = lane >> 2, t = lane & 3;
    const int li = lane >> 3, lj = lane & 7;
    const int h = blockIdx.y;
    const int qBase = blockIdx.x * 128;
    const int hoff = h * DK;
    const int m0 = wid * 16;
    const int NT = S_LEN / 64;

    // stage Q tile (single fp16)
    #pragma unroll
    for (int p = 0; p < 4; p++) {
        const int c = tid + p * 256;
        const int r = c >> 3, off = (c & 7) * 8;
        *(uint4*)&Qs[r * AP + off] =
            *(const uint4*)&Qf[(size_t)(qBase + r) * DMODEL + hoff + off];
    }

    // per-thread staging coordinates (same for every tile)
    const int sr0 = tid >> 3,          soff0 = (tid & 7) * 8;
    const int sr1 = (tid + 256) >> 3,  soff1 = ((tid + 256) & 7) * 8;
    const size_t gbase0 = (size_t)sr0 * DMODEL + hoff + soff0;
    const size_t gbase1 = (size_t)sr1 * DMODEL + hoff + soff1;

    // prefetch tile 0 into registers
    uint4 rK[2], rVh[2], rVl[2];
    rK[0]  = *(const uint4*)&Kf[gbase0];
    rVh[0] = *(const uint4*)&Vh[gbase0];
    rVl[0] = *(const uint4*)&Vl[gbase0];
    rK[1]  = *(const uint4*)&Kf[gbase1];
    rVh[1] = *(const uint4*)&Vh[gbase1];
    rVl[1] = *(const uint4*)&Vl[gbase1];

    float Oa[8][4];
    #pragma unroll
    for (int a = 0; a < 8; a++)
        #pragma unroll
        for (int b = 0; b < 4; b++) Oa[a][b] = 0.f;
    float mrow0 = -1e30f, mrow1 = -1e30f, lrow0 = 0.f, lrow1 = 0.f;
    const float C1 = 0.125f;  // 1/sqrt(DK)

    for (int it = 0; it < NT; it++) {
        // store current tile (previous iteration's trailing barrier protects WAR)
        *(uint4*)&Ks[sr0 * AP + soff0]  = rK[0];
        *(uint4*)&VHs[sr0 * AP + soff0] = rVh[0];
        *(uint4*)&VLs[sr0 * AP + soff0] = rVl[0];
        *(uint4*)&Ks[sr1 * AP + soff1]  = rK[1];
        *(uint4*)&VHs[sr1 * AP + soff1] = rVh[1];
        *(uint4*)&VLs[sr1 * AP + soff1] = rVl[1];
        __syncthreads();

        // prefetch next tile (latency hidden behind compute below)
        if (it + 1 < NT) {
            const size_t go = (size_t)(it + 1) * 64 * DMODEL;
            rK[0]  = *(const uint4*)&Kf[go + gbase0];
            rVh[0] = *(const uint4*)&Vh[go + gbase0];
            rVl[0] = *(const uint4*)&Vl[go + gbase0];
            rK[1]  = *(const uint4*)&Kf[go + gbase1];
            rVh[1] = *(const uint4*)&Vh[go + gbase1];
            rVl[1] = *(const uint4*)&Vl[go + gbase1];
        }

        // ---- S = Q K^T (single-term fp16) ----
        float SP[8][4];
        #pragma unroll
        for (int a = 0; a < 8; a++)
            #pragma unroll
            for (int b = 0; b < 4; b++) SP[a][b] = 0.f;

        #pragma unroll
        for (int kk = 0; kk < 4; kk++) {
            unsigned q4[4];
            const int qrow = m0 + (li & 1) * 8 + lj;
            const int qcol = kk * 16 + (li >> 1) * 8;
            LDSM4(q4, saddr(&Qs[qrow * AP + qcol]));
            #pragma unroll
            for (int ntp = 0; ntp < 4; ntp++) {
                const int krow = ntp * 16 + (li >> 1) * 8 + lj;
                const int kcol = kk * 16 + (li & 1) * 8;
                unsigned bh[4];
                LDSM4(bh, saddr(&Ks[krow * AP + kcol]));
                MMA_F16(SP[2 * ntp],     q4, bh[0], bh[1]);
                MMA_F16(SP[2 * ntp + 1], q4, bh[2], bh[3]);
            }
        }

        // ---- online softmax (rows g and g+8) ----
        float mx0 = -1e30f, mx1 = -1e30f;
        #pragma unroll
        for (int nt = 0; nt < 8; nt++) {
            mx0 = fmaxf(mx0, fmaxf(SP[nt][0], SP[nt][1]));
            mx1 = fmaxf(mx1, fmaxf(SP[nt][2], SP[nt][3]));
        }
        mx0 = fmaxf(mx0, __shfl_xor_sync(0xffffffffu, mx0, 1));
        mx0 = fmaxf(mx0, __shfl_xor_sync(0xffffffffu, mx0, 2));
        mx1 = fmaxf(mx1, __shfl_xor_sync(0xffffffffu, mx1, 1));
        mx1 = fmaxf(mx1, __shfl_xor_sync(0xffffffffu, mx1, 2));

        const float mn0 = fmaxf(mrow0, mx0 * C1);
        const float mn1 = fmaxf(mrow1, mx1 * C1);
        const float cor0 = __expf(mrow0 - mn0);
        const float cor1 = __expf(mrow1 - mn1);
        mrow0 = mn0; mrow1 = mn1;

        float rs0 = 0.f, rs1 = 0.f;
        #pragma unroll
        for (int nt = 0; nt < 8; nt++) {
            SP[nt][0] = __expf(fmaf(SP[nt][0], C1, -mn0)); rs0 += SP[nt][0];
            SP[nt][1] = __expf(fmaf(SP[nt][1], C1, -mn0)); rs0 += SP[nt][1];
            SP[nt][2] = __expf(fmaf(SP[nt][2], C1, -mn1)); rs1 += SP[nt][2];
            SP[nt][3] = __expf(fmaf(SP[nt][3], C1, -mn1)); rs1 += SP[nt][3];
        }
        rs0 += __shfl_xor_sync(0xffffffffu, rs0, 1);
        rs0 += __shfl_xor_sync(0xffffffffu, rs0, 2);
        rs1 += __shfl_xor_sync(0xffffffffu, rs1, 1);
        rs1 += __shfl_xor_sync(0xffffffffu, rs1, 2);
        lrow0 = lrow0 * cor0 + rs0;
        lrow1 = lrow1 * cor1 + rs1;
        #pragma unroll
        for (int nt = 0; nt < 8; nt++) {
            Oa[nt][0] *= cor0; Oa[nt][1] *= cor0;
            Oa[nt][2] *= cor1; Oa[nt][3] *= cor1;
        }

        // ---- O += P V (3-term fp16 split) ----
        #pragma unroll
        for (int kk = 0; kk < 4; kk++) {
            unsigned aph[4], apl[4];
            split_pack_h(SP[2 * kk][0],     SP[2 * kk][1],     aph[0], apl[0]);
            split_pack_h(SP[2 * kk][2],     SP[2 * kk][3],     aph[1], apl[1]);
            split_pack_h(SP[2 * kk + 1][0], SP[2 * kk + 1][1], aph[2], apl[2]);
            split_pack_h(SP[2 * kk + 1][2], SP[2 * kk + 1][3], aph[3], apl[3]);
            #pragma unroll
            for (int ntp = 0; ntp < 4; ntp++) {
                const int vrow = kk * 16 + (li & 1) * 8 + lj;
                const int vcol = ntp * 16 + (li >> 1) * 8;
                unsigned bh[4], bl[4];
                LDSM4T(bh, saddr(&VHs[vrow * AP + vcol]));
                LDSM4T(bl, saddr(&VLs[vrow * AP + vcol]));
                MMA_F16(Oa[2 * ntp],     aph, bh[0], bh[1]);
                MMA_F16(Oa[2 * ntp],     apl, bh[0], bh[1]);
                MMA_F16(Oa[2 * ntp],     aph, bl[0], bl[1]);
                MMA_F16(Oa[2 * ntp + 1], aph, bh[2], bh[3]);
                MMA_F16(Oa[2 * ntp + 1], apl, bh[2], bh[3]);
                MMA_F16(Oa[2 * ntp + 1], aph, bl[2], bl[3]);
            }
        }
        __syncthreads();   // all reads done before next iteration's STS
    }

    // ---- epilogue: normalize, split-store ctx ----
    const float il0 = 1.f / lrow0;
    const float il1 = 1.f / lrow1;
    const int r0 = qBase + m0 + g;
    #pragma unroll
    for (int nt = 0; nt < 8; nt++) {
        const int c = hoff + nt * 8 + 2 * t;
        store_split_h(Ch, Cl, (size_t)r0 * DMODEL + c,       Oa[nt][0] * il0, Oa[nt][1] * il0);
        store_split_h(Ch, Cl, (size_t)(r0 + 8) * DMODEL + c, Oa[nt][2] * il1, Oa[nt][3] * il1);
    }
}

// ---------------------------------------------------------------------------
extern "C" void kernel_launch(void* const* d_in, const int* in_sizes, int n_in,
                              void* d_out, int out_size)
{
    const float* q  = (const float*)d_in[0];
    const float* k  = (const float*)d_in[1];
    const float* v  = (const float*)d_in[2];
    const float* Wq = (const float*)d_in[3];
    const float* bq = (const float*)d_in[4];
    const float* Wk = (const float*)d_in[5];
    const float* bk = (const float*)d_in[6];
    const float* Wv = (const float*)d_in[7];
    const float* bv = (const float*)d_in[8];
    const float* Wo = (const float*)d_in[9];
    const float* bo = (const float*)d_in[10];
    float* out = (float*)d_out;

    h16* B;
    cudaGetSymbolAddress((void**)&B, g_buf);
    h16* q16  = B;
    h16* k16  = B + SDe;
    h16* Wq16 = B + 2 * SDe;
    h16* Wk16 = B + 2 * SDe + DDe;
    h16* vh   = B + 2 * SDe + 2 * DDe;
    h16* vl   = B + 3 * SDe + 2 * DDe;
    h16* Wvh  = B + 4 * SDe + 2 * DDe;
    h16* Wvl  = B + 4 * SDe + 3 * DDe;
    h16* Woh  = B + 4 * SDe + 4 * DDe;
    h16* Wol  = B + 4 * SDe + 5 * DDe;
    h16* Qf   = B + 4 * SDe + 6 * DDe;
    h16* Kf   = B + 5 * SDe + 6 * DDe;
    h16* Vph  = B + 6 * SDe + 6 * DDe;
    h16* Vpl  = B + 7 * SDe + 6 * DDe;
    h16* Ch   = B + 8 * SDe + 6 * DDe;
    h16* Cl   = B + 9 * SDe + 6 * DDe;

    cudaFuncSetAttribute(proj_qkv, cudaFuncAttributeMaxDynamicSharedMemorySize, 49152);
    cudaFuncSetAttribute(proj_out, cudaFuncAttributeMaxDynamicSharedMemorySize, 49152);
    cudaFuncSetAttribute(attn_f16, cudaFuncAttributeMaxDynamicSharedMemorySize, 46080);

    const int T = 256;
    const int nSD4 = (int)(SDe / 4), nDD4 = (int)(DDe / 4);

    dim3 gc1((unsigned)(nSD4 / T), 1, 4);   // q, k, Wq, Wk -> single fp16
    cvt_single_z<<<gc1, T>>>(q, k, Wq, Wk, q16, k16, Wq16, Wk16,
                             nSD4, nSD4, nDD4, nDD4);
    dim3 gc2((unsigned)(nSD4 / T), 1, 3);   // v, Wv, Wo -> split fp16
    cvt_split_z<<<gc2, T>>>(v, Wv, Wo, vh, vl, Wvh, Wvl, Woh, Wol,
                            nSD4, nDD4, nDD4);

    // fused QKV projections (z: 0=Q single, 1=K single, 2=V split)
    dim3 gp(DMODEL / 128, S_LEN / 128, 3);
    proj_qkv<<<gp, 256, 49152>>>(q16, k16, Wq16, Wk16, bq, bk, Qf, Kf,
                                 vh, vl, Wvh, Wvl, bv, Vph, Vpl);

    // attention
    dim3 ga(S_LEN / 128, NHEAD, 1);
    attn_f16<<<ga, 256, 46080>>>(Qf, Kf, Vph, Vpl, Ch, Cl);

    // output projection
    dim3 go(DMODEL / 128, S_LEN / 128, 1);
    proj_out<<<go, 256, 49152>>>(Ch, Cl, Woh, Wol, bo, out);
}

// round 16
// speedup vs baseline: 2.5755x; 1.2471x over previous
#include <cuda_runtime.h>
#include <cuda_fp16.h>
#include <math.h>

// ---------------------------------------------------------------------------
// MultiHeadAttention via fp16 tensor cores (mma.sync m16n8k16.f16, fp32 acc).
// Precision plan (r15):
//   Q/K proj + QK^T : single fp16        (error -> softmax exponents)
//   V proj + V side of PV : single fp16  (error averaged by softmax weights)
//   P side of PV : 2-term split          (P hi/lo vs single V)
//   ctx + out proj : 3-term split        (1:1 path, fully protected)
// No tcgen05 (compute_103 PTX target), no cp.async (container failures).
// ---------------------------------------------------------------------------

#define S_LEN  4096
#define DMODEL 1024
#define NHEAD  16
#define DK     64

typedef __half  h16;
typedef __half2 h162;

#define SDe ((size_t)S_LEN * DMODEL)    // 4194304
#define DDe ((size_t)DMODEL * DMODEL)   // 1048576

__device__ h16 g_buf[67108864];         // 128 MB scratch (8*SD + 5*DD used)

// ---------------------------------------------------------------------------
__device__ __forceinline__ unsigned saddr(const void* p) {
    return (unsigned)__cvta_generic_to_shared(p);
}

#define LDSM4(R, A)                                                            \
    asm volatile("ldmatrix.sync.aligned.m8n8.x4.shared.b16 {%0,%1,%2,%3}, [%4];" \
                 : "=r"((R)[0]), "=r"((R)[1]), "=r"((R)[2]), "=r"((R)[3])      \
                 : "r"(A))
#define LDSM4T(R, A)                                                           \
    asm volatile("ldmatrix.sync.aligned.m8n8.x4.trans.shared.b16 {%0,%1,%2,%3}, [%4];" \
                 : "=r"((R)[0]), "=r"((R)[1]), "=r"((R)[2]), "=r"((R)[3])      \
                 : "r"(A))
#define MMA_F16(C, A, B0, B1)                                                  \
    asm volatile("mma.sync.aligned.m16n8k16.row.col.f32.f16.f16.f32 "          \
                 "{%0,%1,%2,%3}, {%4,%5,%6,%7}, {%8,%9}, {%0,%1,%2,%3};"       \
                 : "+f"((C)[0]), "+f"((C)[1]), "+f"((C)[2]), "+f"((C)[3])      \
                 : "r"((A)[0]), "r"((A)[1]), "r"((A)[2]), "r"((A)[3]),         \
                   "r"(B0), "r"(B1))

__device__ __forceinline__ void store_split_h(h16* __restrict__ H, h16* __restrict__ L,
                                              size_t idx, float a, float b)
{
    h16 ha = __float2half_rn(a), hb = __float2half_rn(b);
    *(h162*)&H[idx] = __halves2half2(ha, hb);
    *(h162*)&L[idx] = __floats2half2_rn(a - __half2float(ha), b - __half2float(hb));
}
__device__ __forceinline__ void split_pack_h(float a, float b, unsigned& hi, unsigned& lo)
{
    h16 ha = __float2half_rn(a), hb = __float2half_rn(b);
    h162 hh = __halves2half2(ha, hb);
    hi = *reinterpret_cast<unsigned*>(&hh);
    h162 ll = __floats2half2_rn(a - __half2float(ha), b - __half2float(hb));
    lo = *reinterpret_cast<unsigned*>(&ll);
}

// ---------------------------------------------------------------------------
// conversions
// ---------------------------------------------------------------------------
__global__ void cvt_single_z(const float* __restrict__ s0, const float* __restrict__ s1,
                             const float* __restrict__ s2, const float* __restrict__ s3,
                             const float* __restrict__ s4, const float* __restrict__ s5,
                             h16* __restrict__ d0, h16* __restrict__ d1,
                             h16* __restrict__ d2, h16* __restrict__ d3,
                             h16* __restrict__ d4, h16* __restrict__ d5,
                             int n0, int n1, int n2, int n3, int n4e, int n5)
{
    const int z = blockIdx.z;
    const float* x = (z == 0) ? s0 : (z == 1) ? s1 : (z == 2) ? s2
                   : (z == 3) ? s3 : (z == 4) ? s4 : s5;
    h16* d = (z == 0) ? d0 : (z == 1) ? d1 : (z == 2) ? d2
           : (z == 3) ? d3 : (z == 4) ? d4 : d5;
    const int n4 = (z == 0) ? n0 : (z == 1) ? n1 : (z == 2) ? n2
                 : (z == 3) ? n3 : (z == 4) ? n4e : n5;
    int idx = blockIdx.x * blockDim.x + threadIdx.x;
    if (idx >= n4) return;
    float4 v = ((const float4*)x)[idx];
    ((h162*)d)[2 * idx]     = __floats2half2_rn(v.x, v.y);
    ((h162*)d)[2 * idx + 1] = __floats2half2_rn(v.z, v.w);
}

__global__ void cvt_split_1(const float* __restrict__ x,
                            h16* __restrict__ h, h16* __restrict__ l, int n4)
{
    int idx = blockIdx.x * blockDim.x + threadIdx.x;
    if (idx >= n4) return;
    float4 v = ((const float4*)x)[idx];
    h16 a0 = __float2half_rn(v.x), a1 = __float2half_rn(v.y);
    h16 a2 = __float2half_rn(v.z), a3 = __float2half_rn(v.w);
    ((h162*)h)[2 * idx]     = __halves2half2(a0, a1);
    ((h162*)h)[2 * idx + 1] = __halves2half2(a2, a3);
    ((h162*)l)[2 * idx]     = __floats2half2_rn(v.x - __half2float(a0),
                                                v.y - __half2float(a1));
    ((h162*)l)[2 * idx + 1] = __floats2half2_rn(v.z - __half2float(a2),
                                                v.w - __half2float(a3));
}

// ---------------------------------------------------------------------------
// GEMM bodies (M=S_LEN, N=K=DMODEL). 128x128 tile, BK=16, 8 warps,
// reg double-buffer, synchronous LDG/STS (proven pattern).
// ---------------------------------------------------------------------------
#define GP 24

__device__ __forceinline__
void gemm_single_body(const h16* __restrict__ A, const h16* __restrict__ W,
                      const float* __restrict__ bias, h16* __restrict__ O,
                      h16* smg)
{
    const int tid  = threadIdx.x;
    const int lane = tid & 31, wid = tid >> 5;
    const int g = lane >> 2, t = lane & 3;
    const int li = lane >> 3, lj = lane & 7;
    const int wm0 = (wid & 3) * 32;
    const int wn0 = (wid >> 2) * 64;
    const int rowBase = blockIdx.y * 128, colBase = blockIdx.x * 128;

    float acc[2][8][4];
    #pragma unroll
    for (int a = 0; a < 2; a++)
        #pragma unroll
        for (int b = 0; b < 8; b++)
            #pragma unroll
            for (int c = 0; c < 4; c++) acc[a][b][c] = 0.f;

    const int lrow = tid >> 1, lhalf = (tid & 1) * 8;
    const h16* pA = A + (size_t)(rowBase + lrow) * DMODEL + lhalf;
    const h16* pW = W + (size_t)(colBase + lrow) * DMODEL + lhalf;
    const int sts = lrow * GP + lhalf;

    uint4 rA = *(const uint4*)pA;
    uint4 rW = *(const uint4*)pW;
    *(uint4*)&smg[0 * 3072 + sts] = rA;
    *(uint4*)&smg[1 * 3072 + sts] = rW;
    __syncthreads();

    const int KS = DMODEL >> 4;
    for (int ks = 0; ks < KS; ks++) {
        const int cur = (ks & 1) * 6144;
        const bool hasNext = (ks + 1 < KS);
        if (hasNext) {
            const int k0 = (ks + 1) << 4;
            rA = *(const uint4*)(pA + k0);
            rW = *(const uint4*)(pW + k0);
        }
        unsigned af[2][4];
        #pragma unroll
        for (int mt = 0; mt < 2; mt++) {
            const int row = wm0 + mt * 16 + (li & 1) * 8 + lj;
            const int col = (li >> 1) * 8;
            LDSM4(af[mt], saddr(&smg[cur + 0 * 3072 + row * GP + col]));
        }
        #pragma unroll
        for (int ntp = 0; ntp < 4; ntp++) {
            const int row = wn0 + ntp * 16 + (li >> 1) * 8 + lj;
            const int col = (li & 1) * 8;
            unsigned bh[4];
            LDSM4(bh, saddr(&smg[cur + 1 * 3072 + row * GP + col]));
            #pragma unroll
            for (int mt = 0; mt < 2; mt++) {
                MMA_F16(acc[mt][2 * ntp],     af[mt], bh[0], bh[1]);
                MMA_F16(acc[mt][2 * ntp + 1], af[mt], bh[2], bh[3]);
            }
        }
        if (hasNext) {
            const int nxt = ((ks + 1) & 1) * 6144;
            *(uint4*)&smg[nxt + 0 * 3072 + sts] = rA;
            *(uint4*)&smg[nxt + 1 * 3072 + sts] = rW;
        }
        __syncthreads();
    }

    #pragma unroll
    for (int mt = 0; mt < 2; mt++) {
        const int r0 = rowBase + wm0 + mt * 16 + g;
        #pragma unroll
        for (int nt = 0; nt < 8; nt++) {
            const int c = colBase + wn0 + nt * 8 + 2 * t;
            const float bb0 = bias[c], bb1 = bias[c + 1];
            *(h162*)&O[(size_t)r0 * DMODEL + c] =
                __floats2half2_rn(acc[mt][nt][0] + bb0, acc[mt][nt][1] + bb1);
            *(h162*)&O[(size_t)(r0 + 8) * DMODEL + c] =
                __floats2half2_rn(acc[mt][nt][2] + bb0, acc[mt][nt][3] + bb1);
        }
    }
}

__device__ __forceinline__
void gemm_split_body(const h16* __restrict__ Ah, const h16* __restrict__ Al,
                     const h16* __restrict__ Bh, const h16* __restrict__ Bl,
                     const float* __restrict__ bias,
                     float* __restrict__ Cf, h16* smg)
{
    const int tid  = threadIdx.x;
    const int lane = tid & 31, wid = tid >> 5;
    const int g = lane >> 2, t = lane & 3;
    const int li = lane >> 3, lj = lane & 7;
    const int wm0 = (wid & 3) * 32;
    const int wn0 = (wid >> 2) * 64;
    const int rowBase = blockIdx.y * 128, colBase = blockIdx.x * 128;

    float acc[2][8][4];
    #pragma unroll
    for (int a = 0; a < 2; a++)
        #pragma unroll
        for (int b = 0; b < 8; b++)
            #pragma unroll
            for (int c = 0; c < 4; c++) acc[a][b][c] = 0.f;

    const int lrow = tid >> 1, lhalf = (tid & 1) * 8;
    const h16* pAh = Ah + (size_t)(rowBase + lrow) * DMODEL + lhalf;
    const h16* pAl = Al + (size_t)(rowBase + lrow) * DMODEL + lhalf;
    const h16* pBh = Bh + (size_t)(colBase + lrow) * DMODEL + lhalf;
    const h16* pBl = Bl + (size_t)(colBase + lrow) * DMODEL + lhalf;
    const int sts = lrow * GP + lhalf;

    uint4 rAh = *(const uint4*)pAh;
    uint4 rAl = *(const uint4*)pAl;
    uint4 rBh = *(const uint4*)pBh;
    uint4 rBl = *(const uint4*)pBl;
    *(uint4*)&smg[0 * 3072 + sts] = rAh;
    *(uint4*)&smg[1 * 3072 + sts] = rAl;
    *(uint4*)&smg[2 * 3072 + sts] = rBh;
    *(uint4*)&smg[3 * 3072 + sts] = rBl;
    __syncthreads();

    const int KS = DMODEL >> 4;
    for (int ks = 0; ks < KS; ks++) {
        const int cur = (ks & 1) * 12288;
        const bool hasNext = (ks + 1 < KS);
        if (hasNext) {
            const int k0 = (ks + 1) << 4;
            rAh = *(const uint4*)(pAh + k0);
            rAl = *(const uint4*)(pAl + k0);
            rBh = *(const uint4*)(pBh + k0);
            rBl = *(const uint4*)(pBl + k0);
        }
        unsigned afh[2][4], afl[2][4];
        #pragma unroll
        for (int mt = 0; mt < 2; mt++) {
            const int row = wm0 + mt * 16 + (li & 1) * 8 + lj;
            const int col = (li >> 1) * 8;
            LDSM4(afh[mt], saddr(&smg[cur + 0 * 3072 + row * GP + col]));
            LDSM4(afl[mt], saddr(&smg[cur + 1 * 3072 + row * GP + col]));
        }
        #pragma unroll
        for (int ntp = 0; ntp < 4; ntp++) {
            const int row = wn0 + ntp * 16 + (li >> 1) * 8 + lj;
            const int col = (li & 1) * 8;
            unsigned bh[4], bl[4];
            LDSM4(bh, saddr(&smg[cur + 2 * 3072 + row * GP + col]));
            LDSM4(bl, saddr(&smg[cur + 3 * 3072 + row * GP + col]));
            #pragma unroll
            for (int mt = 0; mt < 2; mt++) {
                MMA_F16(acc[mt][2 * ntp],     afh[mt], bh[0], bh[1]);
                MMA_F16(acc[mt][2 * ntp],     afl[mt], bh[0], bh[1]);
                MMA_F16(acc[mt][2 * ntp],     afh[mt], bl[0], bl[1]);
                MMA_F16(acc[mt][2 * ntp + 1], afh[mt], bh[2], bh[3]);
                MMA_F16(acc[mt][2 * ntp + 1], afl[mt], bh[2], bh[3]);
                MMA_F16(acc[mt][2 * ntp + 1], afh[mt], bl[2], bl[3]);
            }
        }
        if (hasNext) {
            const int nxt = ((ks + 1) & 1) * 12288;
            *(uint4*)&smg[nxt + 0 * 3072 + sts] = rAh;
            *(uint4*)&smg[nxt + 1 * 3072 + sts] = rAl;
            *(uint4*)&smg[nxt + 2 * 3072 + sts] = rBh;
            *(uint4*)&smg[nxt + 3 * 3072 + sts] = rBl;
        }
        __syncthreads();
    }

    #pragma unroll
    for (int mt = 0; mt < 2; mt++) {
        const int r0 = rowBase + wm0 + mt * 16 + g;
        #pragma unroll
        for (int nt = 0; nt < 8; nt++) {
            const int c = colBase + wn0 + nt * 8 + 2 * t;
            const float bb0 = bias[c], bb1 = bias[c + 1];
            *(float2*)&Cf[(size_t)r0 * DMODEL + c] =
                make_float2(acc[mt][nt][0] + bb0, acc[mt][nt][1] + bb1);
            *(float2*)&Cf[(size_t)(r0 + 8) * DMODEL + c] =
                make_float2(acc[mt][nt][2] + bb0, acc[mt][nt][3] + bb1);
        }
    }
}

// ---------------------------------------------------------------------------
// Fused QKV projections: all single-term (z selects Q/K/V)
// ---------------------------------------------------------------------------
__global__ __launch_bounds__(256, 2)
void proj_qkv(const h16* __restrict__ q16, const h16* __restrict__ k16,
              const h16* __restrict__ v16,
              const h16* __restrict__ Wq16, const h16* __restrict__ Wk16,
              const h16* __restrict__ Wv16,
              const float* __restrict__ bq, const float* __restrict__ bk,
              const float* __restrict__ bv,
              h16* __restrict__ Qf, h16* __restrict__ Kf, h16* __restrict__ Vf)
{
    extern __shared__ h16 smg[];
    const int z = blockIdx.z;
    const h16* A = (z == 0) ? q16 : (z == 1) ? k16 : v16;
    const h16* W = (z == 0) ? Wq16 : (z == 1) ? Wk16 : Wv16;
    const float* b = (z == 0) ? bq : (z == 1) ? bk : bv;
    h16* O = (z == 0) ? Qf : (z == 1) ? Kf : Vf;
    gemm_single_body(A, W, b, O, smg);
}

// output projection (3-term split, fp32 out)
__global__ __launch_bounds__(256, 2)
void proj_out(const h16* __restrict__ Ch, const h16* __restrict__ Cl,
              const h16* __restrict__ Woh, const h16* __restrict__ Wol,
              const float* __restrict__ bo, float* __restrict__ out)
{
    extern __shared__ h16 smg[];
    gemm_split_body(Ch, Cl, Woh, Wol, bo, out, smg);
}

// ---------------------------------------------------------------------------
// Flash attention: Q,K,V single fp16; P 2-term split vs single V.
// Br=128, Bc=64, 8 warps, K/V register prefetch.
// smem: Q 128x72 + (K,V) 64x72 = 36864 B.
// ---------------------------------------------------------------------------
#define AP 72

__global__ __launch_bounds__(256, 2)
void attn_f16(const h16* __restrict__ Qf, const h16* __restrict__ Kf,
              const h16* __restrict__ Vf,
              h16* __restrict__ Ch, h16* __restrict__ Cl)
{
    extern __shared__ h16 sma[];
    h16* Qs = sma;              // 128*72 = 9216 el
    h16* Ks = sma + 9216;       // 64*72 = 4608 el
    h16* Vs = sma + 13824;

    const int tid = threadIdx.x, lane = tid & 31, wid = tid >> 5;
    const int g = lane >> 2, t = lane & 3;
    const int li = lane >> 3, lj = lane & 7;
    const int h = blockIdx.y;
    const int qBase = blockIdx.x * 128;
    const int hoff = h * DK;
    const int m0 = wid * 16;
    const int NT = S_LEN / 64;

    // stage Q tile
    #pragma unroll
    for (int p = 0; p < 4; p++) {
        const int c = tid + p * 256;
        const int r = c >> 3, off = (c & 7) * 8;
        *(uint4*)&Qs[r * AP + off] =
            *(const uint4*)&Qf[(size_t)(qBase + r) * DMODEL + hoff + off];
    }

    // per-thread staging coordinates
    const int sr0 = tid >> 3,          soff0 = (tid & 7) * 8;
    const int sr1 = (tid + 256) >> 3,  soff1 = ((tid + 256) & 7) * 8;
    const size_t gbase0 = (size_t)sr0 * DMODEL + hoff + soff0;
    const size_t gbase1 = (size_t)sr1 * DMODEL + hoff + soff1;

    // prefetch tile 0
    uint4 rK[2], rV[2];
    rK[0] = *(const uint4*)&Kf[gbase0];
    rV[0] = *(const uint4*)&Vf[gbase0];
    rK[1] = *(const uint4*)&Kf[gbase1];
    rV[1] = *(const uint4*)&Vf[gbase1];

    float Oa[8][4];
    #pragma unroll
    for (int a = 0; a < 8; a++)
        #pragma unroll
        for (int b = 0; b < 4; b++) Oa[a][b] = 0.f;
    float mrow0 = -1e30f, mrow1 = -1e30f, lrow0 = 0.f, lrow1 = 0.f;
    const float C1 = 0.125f;  // 1/sqrt(DK)

    for (int it = 0; it < NT; it++) {
        *(uint4*)&Ks[sr0 * AP + soff0] = rK[0];
        *(uint4*)&Vs[sr0 * AP + soff0] = rV[0];
        *(uint4*)&Ks[sr1 * AP + soff1] = rK[1];
        *(uint4*)&Vs[sr1 * AP + soff1] = rV[1];
        __syncthreads();

        if (it + 1 < NT) {
            const size_t go = (size_t)(it + 1) * 64 * DMODEL;
            rK[0] = *(const uint4*)&Kf[go + gbase0];
            rV[0] = *(const uint4*)&Vf[go + gbase0];
            rK[1] = *(const uint4*)&Kf[go + gbase1];
            rV[1] = *(const uint4*)&Vf[go + gbase1];
        }

        // ---- S = Q K^T (single-term) ----
        float SP[8][4];
        #pragma unroll
        for (int a = 0; a < 8; a++)
            #pragma unroll
            for (int b = 0; b < 4; b++) SP[a][b] = 0.f;

        #pragma unroll
        for (int kk = 0; kk < 4; kk++) {
            unsigned q4[4];
            const int qrow = m0 + (li & 1) * 8 + lj;
            const int qcol = kk * 16 + (li >> 1) * 8;
            LDSM4(q4, saddr(&Qs[qrow * AP + qcol]));
            #pragma unroll
            for (int ntp = 0; ntp < 4; ntp++) {
                const int krow = ntp * 16 + (li >> 1) * 8 + lj;
                const int kcol = kk * 16 + (li & 1) * 8;
                unsigned bh[4];
                LDSM4(bh, saddr(&Ks[krow * AP + kcol]));
                MMA_F16(SP[2 * ntp],     q4, bh[0], bh[1]);
                MMA_F16(SP[2 * ntp + 1], q4, bh[2], bh[3]);
            }
        }

        // ---- online softmax (rows g and g+8) ----
        float mx0 = -1e30f, mx1 = -1e30f;
        #pragma unroll
        for (int nt = 0; nt < 8; nt++) {
            mx0 = fmaxf(mx0, fmaxf(SP[nt][0], SP[nt][1]));
            mx1 = fmaxf(mx1, fmaxf(SP[nt][2], SP[nt][3]));
        }
        mx0 = fmaxf(mx0, __shfl_xor_sync(0xffffffffu, mx0, 1));
        mx0 = fmaxf(mx0, __shfl_xor_sync(0xffffffffu, mx0, 2));
        mx1 = fmaxf(mx1, __shfl_xor_sync(0xffffffffu, mx1, 1));
        mx1 = fmaxf(mx1, __shfl_xor_sync(0xffffffffu, mx1, 2));

        const float mn0 = fmaxf(mrow0, mx0 * C1);
        const float mn1 = fmaxf(mrow1, mx1 * C1);
        const float cor0 = __expf(mrow0 - mn0);
        const float cor1 = __expf(mrow1 - mn1);
        mrow0 = mn0; mrow1 = mn1;

        float rs0 = 0.f, rs1 = 0.f;
        #pragma unroll
        for (int nt = 0; nt < 8; nt++) {
            SP[nt][0] = __expf(fmaf(SP[nt][0], C1, -mn0)); rs0 += SP[nt][0];
            SP[nt][1] = __expf(fmaf(SP[nt][1], C1, -mn0)); rs0 += SP[nt][1];
            SP[nt][2] = __expf(fmaf(SP[nt][2], C1, -mn1)); rs1 += SP[nt][2];
            SP[nt][3] = __expf(fmaf(SP[nt][3], C1, -mn1)); rs1 += SP[nt][3];
        }
        rs0 += __shfl_xor_sync(0xffffffffu, rs0, 1);
        rs0 += __shfl_xor_sync(0xffffffffu, rs0, 2);
        rs1 += __shfl_xor_sync(0xffffffffu, rs1, 1);
        rs1 += __shfl_xor_sync(0xffffffffu, rs1, 2);
        lrow0 = lrow0 * cor0 + rs0;
        lrow1 = lrow1 * cor1 + rs1;
        #pragma unroll
        for (int nt = 0; nt < 8; nt++) {
            Oa[nt][0] *= cor0; Oa[nt][1] *= cor0;
            Oa[nt][2] *= cor1; Oa[nt][3] *= cor1;
        }

        // ---- O += P V (P hi/lo split vs single V) ----
        #pragma unroll
        for (int kk = 0; kk < 4; kk++) {
            unsigned aph[4], apl[4];
            split_pack_h(SP[2 * kk][0],     SP[2 * kk][1],     aph[0], apl[0]);
            split_pack_h(SP[2 * kk][2],     SP[2 * kk][3],     aph[1], apl[1]);
            split_pack_h(SP[2 * kk + 1][0], SP[2 * kk + 1][1], aph[2], apl[2]);
            split_pack_h(SP[2 * kk + 1][2], SP[2 * kk + 1][3], aph[3], apl[3]);
            #pragma unroll
            for (int ntp = 0; ntp < 4; ntp++) {
                const int vrow = kk * 16 + (li & 1) * 8 + lj;
                const int vcol = ntp * 16 + (li >> 1) * 8;
                unsigned bh[4];
                LDSM4T(bh, saddr(&Vs[vrow * AP + vcol]));
                MMA_F16(Oa[2 * ntp],     aph, bh[0], bh[1]);
                MMA_F16(Oa[2 * ntp],     apl, bh[0], bh[1]);
                MMA_F16(Oa[2 * ntp + 1], aph, bh[2], bh[3]);
                MMA_F16(Oa[2 * ntp + 1], apl, bh[2], bh[3]);
            }
        }
        __syncthreads();   // all reads done before next iteration's STS
    }

    // ---- epilogue: normalize, split-store ctx ----
    const float il0 = 1.f / lrow0;
    const float il1 = 1.f / lrow1;
    const int r0 = qBase + m0 + g;
    #pragma unroll
    for (int nt = 0; nt < 8; nt++) {
        const int c = hoff + nt * 8 + 2 * t;
        store_split_h(Ch, Cl, (size_t)r0 * DMODEL + c,       Oa[nt][0] * il0, Oa[nt][1] * il0);
        store_split_h(Ch, Cl, (size_t)(r0 + 8) * DMODEL + c, Oa[nt][2] * il1, Oa[nt][3] * il1);
    }
}

// ---------------------------------------------------------------------------
extern "C" void kernel_launch(void* const* d_in, const int* in_sizes, int n_in,
                              void* d_out, int out_size)
{
    const float* q  = (const float*)d_in[0];
    const float* k  = (const float*)d_in[1];
    const float* v  = (const float*)d_in[2];
    const float* Wq = (const float*)d_in[3];
    const float* bq = (const float*)d_in[4];
    const float* Wk = (const float*)d_in[5];
    const float* bk = (const float*)d_in[6];
    const float* Wv = (const float*)d_in[7];
    const float* bv = (const float*)d_in[8];
    const float* Wo = (const float*)d_in[9];
    const float* bo = (const float*)d_in[10];
    float* out = (float*)d_out;

    h16* B;
    cudaGetSymbolAddress((void**)&B, g_buf);
    h16* q16  = B;
    h16* k16  = B + SDe;
    h16* v16  = B + 2 * SDe;
    h16* Wq16 = B + 3 * SDe;
    h16* Wk16 = B + 3 * SDe + DDe;
    h16* Wv16 = B + 3 * SDe + 2 * DDe;
    h16* Woh  = B + 3 * SDe + 3 * DDe;
    h16* Wol  = B + 3 * SDe + 4 * DDe;
    h16* Qf   = B + 3 * SDe + 5 * DDe;
    h16* Kf   = B + 4 * SDe + 5 * DDe;
    h16* Vf   = B + 5 * SDe + 5 * DDe;
    h16* Ch   = B + 6 * SDe + 5 * DDe;
    h16* Cl   = B + 7 * SDe + 5 * DDe;

    cudaFuncSetAttribute(proj_qkv, cudaFuncAttributeMaxDynamicSharedMemorySize, 24576);
    cudaFuncSetAttribute(proj_out, cudaFuncAttributeMaxDynamicSharedMemorySize, 49152);
    cudaFuncSetAttribute(attn_f16, cudaFuncAttributeMaxDynamicSharedMemorySize, 36864);

    const int T = 256;
    const int nSD4 = (int)(SDe / 4), nDD4 = (int)(DDe / 4);

    // q,k,v,Wq,Wk,Wv -> single fp16 (grid.x sized for the largest = SD)
    dim3 gc1((unsigned)(nSD4 / T), 1, 6);
    cvt_single_z<<<gc1, T>>>(q, k, v, Wq, Wk, Wv,
                             q16, k16, v16, Wq16, Wk16, Wv16,
                             nSD4, nSD4, nSD4, nDD4, nDD4, nDD4);
    // Wo -> split fp16
    cvt_split_1<<<(unsigned)(nDD4 / T), T>>>(Wo, Woh, Wol, nDD4);

    // fused QKV projections (all single-term)
    dim3 gp(DMODEL / 128, S_LEN / 128, 3);
    proj_qkv<<<gp, 256, 24576>>>(q16, k16, v16, Wq16, Wk16, Wv16,
                                 bq, bk, bv, Qf, Kf, Vf);

    // attention
    dim3 ga(S_LEN / 128, NHEAD, 1);
    attn_f16<<<ga, 256, 36864>>>(Qf, Kf, Vf, Ch, Cl);

    // output projection (3-term split, fp32 out)
    dim3 go(DMODEL / 128, S_LEN / 128, 1);
    proj_out<<<go, 256, 49152>>>(Ch, Cl, Woh, Wol, bo, out);
}

// round 17
// speedup vs baseline: 2.8001x; 1.0872x over previous
#include <cuda_runtime.h>
#include <cuda_fp16.h>
#include <math.h>

// ---------------------------------------------------------------------------
// MultiHeadAttention via fp16 tensor cores (mma.sync m16n8k16.f16, fp32 acc).
// Precision plan (r17, calibrated error model):
//   Q/K/V proj + QK^T + PV : single fp16 (exponent-space / softmax-averaged)
//   ctx + out proj         : 3-term split (1:1 path)
// Conversions fused into GEMM staging (projections read fp32 directly).
// No tcgen05 (compute_103 PTX target), no cp.async (container failures).
// ---------------------------------------------------------------------------

#define S_LEN  4096
#define DMODEL 1024
#define NHEAD  16
#define DK     64

typedef __half  h16;
typedef __half2 h162;

#define SDe ((size_t)S_LEN * DMODEL)    // 4194304
#define DDe ((size_t)DMODEL * DMODEL)   // 1048576

__device__ h16 g_buf[67108864];         // scratch (5*SD used)

// ---------------------------------------------------------------------------
__device__ __forceinline__ unsigned saddr(const void* p) {
    return (unsigned)__cvta_generic_to_shared(p);
}
__device__ __forceinline__ unsigned pk2(float a, float b) {
    h162 h = __floats2half2_rn(a, b);
    return *reinterpret_cast<unsigned*>(&h);
}

#define LDSM4(R, A)                                                            \
    asm volatile("ldmatrix.sync.aligned.m8n8.x4.shared.b16 {%0,%1,%2,%3}, [%4];" \
                 : "=r"((R)[0]), "=r"((R)[1]), "=r"((R)[2]), "=r"((R)[3])      \
                 : "r"(A))
#define LDSM4T(R, A)                                                           \
    asm volatile("ldmatrix.sync.aligned.m8n8.x4.trans.shared.b16 {%0,%1,%2,%3}, [%4];" \
                 : "=r"((R)[0]), "=r"((R)[1]), "=r"((R)[2]), "=r"((R)[3])      \
                 : "r"(A))
#define MMA_F16(C, A, B0, B1)                                                  \
    asm volatile("mma.sync.aligned.m16n8k16.row.col.f32.f16.f16.f32 "          \
                 "{%0,%1,%2,%3}, {%4,%5,%6,%7}, {%8,%9}, {%0,%1,%2,%3};"       \
                 : "+f"((C)[0]), "+f"((C)[1]), "+f"((C)[2]), "+f"((C)[3])      \
                 : "r"((A)[0]), "r"((A)[1]), "r"((A)[2]), "r"((A)[3]),         \
                   "r"(B0), "r"(B1))

__device__ __forceinline__ void store_split_h(h16* __restrict__ H, h16* __restrict__ L,
                                              size_t idx, float a, float b)
{
    h16 ha = __float2half_rn(a), hb = __float2half_rn(b);
    *(h162*)&H[idx] = __halves2half2(ha, hb);
    *(h162*)&L[idx] = __floats2half2_rn(a - __half2float(ha), b - __half2float(hb));
}

// ---------------------------------------------------------------------------
// Single-term GEMM, fp32 inputs converted during staging.
// C[M,N] = A[M,K]*W[N,K]^T + bias, fp16 out. 128x128, BK=16, 8 warps.
// smem: 2 buf x 2 arr x 128x24 fp16 = 24576 B
// ---------------------------------------------------------------------------
#define GP 24

__device__ __forceinline__
void gemm_single_f32(const float* __restrict__ A, const float* __restrict__ W,
                     const float* __restrict__ bias, h16* __restrict__ O,
                     h16* smg)
{
    const int tid  = threadIdx.x;
    const int lane = tid & 31, wid = tid >> 5;
    const int g = lane >> 2, t = lane & 3;
    const int li = lane >> 3, lj = lane & 7;
    const int wm0 = (wid & 3) * 32;
    const int wn0 = (wid >> 2) * 64;
    const int rowBase = blockIdx.y * 128, colBase = blockIdx.x * 128;

    float acc[2][8][4];
    #pragma unroll
    for (int a = 0; a < 2; a++)
        #pragma unroll
        for (int b = 0; b < 8; b++)
            #pragma unroll
            for (int c = 0; c < 4; c++) acc[a][b][c] = 0.f;

    const int lrow = tid >> 1, lhalf = (tid & 1) * 8;
    const float* pA = A + (size_t)(rowBase + lrow) * DMODEL + lhalf;
    const float* pW = W + (size_t)(colBase + lrow) * DMODEL + lhalf;
    const int sts = lrow * GP + lhalf;

    auto cvt8 = [](const float* p) {
        float4 f0 = *(const float4*)p;
        float4 f1 = *(const float4*)(p + 4);
        return make_uint4(pk2(f0.x, f0.y), pk2(f0.z, f0.w),
                          pk2(f1.x, f1.y), pk2(f1.z, f1.w));
    };

    uint4 rA = cvt8(pA);
    uint4 rW = cvt8(pW);
    *(uint4*)&smg[0 * 3072 + sts] = rA;
    *(uint4*)&smg[1 * 3072 + sts] = rW;
    __syncthreads();

    const int KS = DMODEL >> 4;
    for (int ks = 0; ks < KS; ks++) {
        const int cur = (ks & 1) * 6144;
        const bool hasNext = (ks + 1 < KS);
        if (hasNext) {
            const int k0 = (ks + 1) << 4;
            rA = cvt8(pA + k0);
            rW = cvt8(pW + k0);
        }
        unsigned af[2][4];
        #pragma unroll
        for (int mt = 0; mt < 2; mt++) {
            const int row = wm0 + mt * 16 + (li & 1) * 8 + lj;
            const int col = (li >> 1) * 8;
            LDSM4(af[mt], saddr(&smg[cur + 0 * 3072 + row * GP + col]));
        }
        #pragma unroll
        for (int ntp = 0; ntp < 4; ntp++) {
            const int row = wn0 + ntp * 16 + (li >> 1) * 8 + lj;
            const int col = (li & 1) * 8;
            unsigned bh[4];
            LDSM4(bh, saddr(&smg[cur + 1 * 3072 + row * GP + col]));
            #pragma unroll
            for (int mt = 0; mt < 2; mt++) {
                MMA_F16(acc[mt][2 * ntp],     af[mt], bh[0], bh[1]);
                MMA_F16(acc[mt][2 * ntp + 1], af[mt], bh[2], bh[3]);
            }
        }
        if (hasNext) {
            const int nxt = ((ks + 1) & 1) * 6144;
            *(uint4*)&smg[nxt + 0 * 3072 + sts] = rA;
            *(uint4*)&smg[nxt + 1 * 3072 + sts] = rW;
        }
        __syncthreads();
    }

    #pragma unroll
    for (int mt = 0; mt < 2; mt++) {
        const int r0 = rowBase + wm0 + mt * 16 + g;
        #pragma unroll
        for (int nt = 0; nt < 8; nt++) {
            const int c = colBase + wn0 + nt * 8 + 2 * t;
            const float bb0 = bias[c], bb1 = bias[c + 1];
            *(h162*)&O[(size_t)r0 * DMODEL + c] =
                __floats2half2_rn(acc[mt][nt][0] + bb0, acc[mt][nt][1] + bb1);
            *(h162*)&O[(size_t)(r0 + 8) * DMODEL + c] =
                __floats2half2_rn(acc[mt][nt][2] + bb0, acc[mt][nt][3] + bb1);
        }
    }
}

__global__ __launch_bounds__(256, 2)
void proj_qkv(const float* __restrict__ q, const float* __restrict__ k,
              const float* __restrict__ v,
              const float* __restrict__ Wq, const float* __restrict__ Wk,
              const float* __restrict__ Wv,
              const float* __restrict__ bq, const float* __restrict__ bk,
              const float* __restrict__ bv,
              h16* __restrict__ Qf, h16* __restrict__ Kf, h16* __restrict__ Vf)
{
    extern __shared__ h16 smg[];
    const int z = blockIdx.z;
    const float* A = (z == 0) ? q : (z == 1) ? k : v;
    const float* W = (z == 0) ? Wq : (z == 1) ? Wk : Wv;
    const float* b = (z == 0) ? bq : (z == 1) ? bk : bv;
    h16* O = (z == 0) ? Qf : (z == 1) ? Kf : Vf;
    gemm_single_f32(A, W, b, O, smg);
}

// ---------------------------------------------------------------------------
// Output projection: ctx (fp16 hi/lo) x Wo (fp32, split during staging),
// 3-term split, fp32 out. smem: 2 buf x 4 arr x 128x24 fp16 = 49152 B
// ---------------------------------------------------------------------------
__global__ __launch_bounds__(256, 2)
void proj_out(const h16* __restrict__ Ah, const h16* __restrict__ Al,
              const float* __restrict__ Wo,
              const float* __restrict__ bias, float* __restrict__ Cf)
{
    extern __shared__ h16 smg[];
    const int tid  = threadIdx.x;
    const int lane = tid & 31, wid = tid >> 5;
    const int g = lane >> 2, t = lane & 3;
    const int li = lane >> 3, lj = lane & 7;
    const int wm0 = (wid & 3) * 32;
    const int wn0 = (wid >> 2) * 64;
    const int rowBase = blockIdx.y * 128, colBase = blockIdx.x * 128;

    float acc[2][8][4];
    #pragma unroll
    for (int a = 0; a < 2; a++)
        #pragma unroll
        for (int b = 0; b < 8; b++)
            #pragma unroll
            for (int c = 0; c < 4; c++) acc[a][b][c] = 0.f;

    const int lrow = tid >> 1, lhalf = (tid & 1) * 8;
    const h16*   pAh = Ah + (size_t)(rowBase + lrow) * DMODEL + lhalf;
    const h16*   pAl = Al + (size_t)(rowBase + lrow) * DMODEL + lhalf;
    const float* pW  = Wo + (size_t)(colBase + lrow) * DMODEL + lhalf;
    const int sts = lrow * GP + lhalf;

    // load 8 fp32 W values -> hi uint4 + lo uint4
    auto cvtW = [](const float* p, uint4& hi, uint4& lo) {
        float f[8];
        *(float4*)(f)     = *(const float4*)p;
        *(float4*)(f + 4) = *(const float4*)(p + 4);
        unsigned h[4], l[4];
        #pragma unroll
        for (int i = 0; i < 4; i++) {
            h16 h0 = __float2half_rn(f[2 * i]);
            h16 h1 = __float2half_rn(f[2 * i + 1]);
            h162 hh = __halves2half2(h0, h1);
            h[i] = *reinterpret_cast<unsigned*>(&hh);
            l[i] = pk2(f[2 * i] - __half2float(h0), f[2 * i + 1] - __half2float(h1));
        }
        hi = make_uint4(h[0], h[1], h[2], h[3]);
        lo = make_uint4(l[0], l[1], l[2], l[3]);
    };

    uint4 rAh = *(const uint4*)pAh;
    uint4 rAl = *(const uint4*)pAl;
    uint4 rBh, rBl;
    cvtW(pW, rBh, rBl);
    *(uint4*)&smg[0 * 3072 + sts] = rAh;
    *(uint4*)&smg[1 * 3072 + sts] = rAl;
    *(uint4*)&smg[2 * 3072 + sts] = rBh;
    *(uint4*)&smg[3 * 3072 + sts] = rBl;
    __syncthreads();

    const int KS = DMODEL >> 4;
    for (int ks = 0; ks < KS; ks++) {
        const int cur = (ks & 1) * 12288;
        const bool hasNext = (ks + 1 < KS);
        if (hasNext) {
            const int k0 = (ks + 1) << 4;
            rAh = *(const uint4*)(pAh + k0);
            rAl = *(const uint4*)(pAl + k0);
            cvtW(pW + k0, rBh, rBl);
        }
        unsigned afh[2][4], afl[2][4];
        #pragma unroll
        for (int mt = 0; mt < 2; mt++) {
            const int row = wm0 + mt * 16 + (li & 1) * 8 + lj;
            const int col = (li >> 1) * 8;
            LDSM4(afh[mt], saddr(&smg[cur + 0 * 3072 + row * GP + col]));
            LDSM4(afl[mt], saddr(&smg[cur + 1 * 3072 + row * GP + col]));
        }
        #pragma unroll
        for (int ntp = 0; ntp < 4; ntp++) {
            const int row = wn0 + ntp * 16 + (li >> 1) * 8 + lj;
            const int col = (li & 1) * 8;
            unsigned bh[4], bl[4];
            LDSM4(bh, saddr(&smg[cur + 2 * 3072 + row * GP + col]));
            LDSM4(bl, saddr(&smg[cur + 3 * 3072 + row * GP + col]));
            #pragma unroll
            for (int mt = 0; mt < 2; mt++) {
                MMA_F16(acc[mt][2 * ntp],     afh[mt], bh[0], bh[1]);
                MMA_F16(acc[mt][2 * ntp],     afl[mt], bh[0], bh[1]);
                MMA_F16(acc[mt][2 * ntp],     afh[mt], bl[0], bl[1]);
                MMA_F16(acc[mt][2 * ntp + 1], afh[mt], bh[2], bh[3]);
                MMA_F16(acc[mt][2 * ntp + 1], afl[mt], bh[2], bh[3]);
                MMA_F16(acc[mt][2 * ntp + 1], afh[mt], bl[2], bl[3]);
            }
        }
        if (hasNext) {
            const int nxt = ((ks + 1) & 1) * 12288;
            *(uint4*)&smg[nxt + 0 * 3072 + sts] = rAh;
            *(uint4*)&smg[nxt + 1 * 3072 + sts] = rAl;
            *(uint4*)&smg[nxt + 2 * 3072 + sts] = rBh;
            *(uint4*)&smg[nxt + 3 * 3072 + sts] = rBl;
        }
        __syncthreads();
    }

    #pragma unroll
    for (int mt = 0; mt < 2; mt++) {
        const int r0 = rowBase + wm0 + mt * 16 + g;
        #pragma unroll
        for (int nt = 0; nt < 8; nt++) {
            const int c = colBase + wn0 + nt * 8 + 2 * t;
            const float bb0 = bias[c], bb1 = bias[c + 1];
            *(float2*)&Cf[(size_t)r0 * DMODEL + c] =
                make_float2(acc[mt][nt][0] + bb0, acc[mt][nt][1] + bb1);
            *(float2*)&Cf[(size_t)(r0 + 8) * DMODEL + c] =
                make_float2(acc[mt][nt][2] + bb0, acc[mt][nt][3] + bb1);
        }
    }
}

// ---------------------------------------------------------------------------
// Flash attention: Q,K,V,P all single fp16; fp32 accumulate everywhere.
// Br=128, Bc=64, 8 warps, K/V register prefetch.
// smem: Q 128x72 + (K,V) 64x72 = 36864 B.
// ---------------------------------------------------------------------------
#define AP 72

__global__ __launch_bounds__(256, 2)
void attn_f16(const h16* __restrict__ Qf, const h16* __restrict__ Kf,
              const h16* __restrict__ Vf,
              h16* __restrict__ Ch, h16* __restrict__ Cl)
{
    extern __shared__ h16 sma[];
    h16* Qs = sma;              // 128*72 = 9216 el
    h16* Ks = sma + 9216;       // 64*72 = 4608 el
    h16* Vs = sma + 13824;

    const int tid = threadIdx.x, lane = tid & 31, wid = tid >> 5;
    const int g = lane >> 2, t = lane & 3;
    const int li = lane >> 3, lj = lane & 7;
    const int h = blockIdx.y;
    const int qBase = blockIdx.x * 128;
    const int hoff = h * DK;
    const int m0 = wid * 16;
    const int NT = S_LEN / 64;

    // stage Q tile
    #pragma unroll
    for (int p = 0; p < 4; p++) {
        const int c = tid + p * 256;
        const int r = c >> 3, off = (c & 7) * 8;
        *(uint4*)&Qs[r * AP + off] =
            *(const uint4*)&Qf[(size_t)(qBase + r) * DMODEL + hoff + off];
    }

    const int sr0 = tid >> 3,          soff0 = (tid & 7) * 8;
    const int sr1 = (tid + 256) >> 3,  soff1 = ((tid + 256) & 7) * 8;
    const size_t gbase0 = (size_t)sr0 * DMODEL + hoff + soff0;
    const size_t gbase1 = (size_t)sr1 * DMODEL + hoff + soff1;

    uint4 rK[2], rV[2];
    rK[0] = *(const uint4*)&Kf[gbase0];
    rV[0] = *(const uint4*)&Vf[gbase0];
    rK[1] = *(const uint4*)&Kf[gbase1];
    rV[1] = *(const uint4*)&Vf[gbase1];

    float Oa[8][4];
    #pragma unroll
    for (int a = 0; a < 8; a++)
        #pragma unroll
        for (int b = 0; b < 4; b++) Oa[a][b] = 0.f;
    float mrow0 = -1e30f, mrow1 = -1e30f, lrow0 = 0.f, lrow1 = 0.f;
    const float C1 = 0.125f;  // 1/sqrt(DK)

    for (int it = 0; it < NT; it++) {
        *(uint4*)&Ks[sr0 * AP + soff0] = rK[0];
        *(uint4*)&Vs[sr0 * AP + soff0] = rV[0];
        *(uint4*)&Ks[sr1 * AP + soff1] = rK[1];
        *(uint4*)&Vs[sr1 * AP + soff1] = rV[1];
        __syncthreads();

        if (it + 1 < NT) {
            const size_t go = (size_t)(it + 1) * 64 * DMODEL;
            rK[0] = *(const uint4*)&Kf[go + gbase0];
            rV[0] = *(const uint4*)&Vf[go + gbase0];
            rK[1] = *(const uint4*)&Kf[go + gbase1];
            rV[1] = *(const uint4*)&Vf[go + gbase1];
        }

        // ---- S = Q K^T ----
        float SP[8][4];
        #pragma unroll
        for (int a = 0; a < 8; a++)
            #pragma unroll
            for (int b = 0; b < 4; b++) SP[a][b] = 0.f;

        #pragma unroll
        for (int kk = 0; kk < 4; kk++) {
            unsigned q4[4];
            const int qrow = m0 + (li & 1) * 8 + lj;
            const int qcol = kk * 16 + (li >> 1) * 8;
            LDSM4(q4, saddr(&Qs[qrow * AP + qcol]));
            #pragma unroll
            for (int ntp = 0; ntp < 4; ntp++) {
                const int krow = ntp * 16 + (li >> 1) * 8 + lj;
                const int kcol = kk * 16 + (li & 1) * 8;
                unsigned bh[4];
                LDSM4(bh, saddr(&Ks[krow * AP + kcol]));
                MMA_F16(SP[2 * ntp],     q4, bh[0], bh[1]);
                MMA_F16(SP[2 * ntp + 1], q4, bh[2], bh[3]);
            }
        }

        // ---- online softmax (rows g and g+8) ----
        float mx0 = -1e30f, mx1 = -1e30f;
        #pragma unroll
        for (int nt = 0; nt < 8; nt++) {
            mx0 = fmaxf(mx0, fmaxf(SP[nt][0], SP[nt][1]));
            mx1 = fmaxf(mx1, fmaxf(SP[nt][2], SP[nt][3]));
        }
        mx0 = fmaxf(mx0, __shfl_xor_sync(0xffffffffu, mx0, 1));
        mx0 = fmaxf(mx0, __shfl_xor_sync(0xffffffffu, mx0, 2));
        mx1 = fmaxf(mx1, __shfl_xor_sync(0xffffffffu, mx1, 1));
        mx1 = fmaxf(mx1, __shfl_xor_sync(0xffffffffu, mx1, 2));

        const float mn0 = fmaxf(mrow0, mx0 * C1);
        const float mn1 = fmaxf(mrow1, mx1 * C1);
        const float cor0 = __expf(mrow0 - mn0);
        const float cor1 = __expf(mrow1 - mn1);
        mrow0 = mn0; mrow1 = mn1;

        float rs0 = 0.f, rs1 = 0.f;
        #pragma unroll
        for (int nt = 0; nt < 8; nt++) {
            SP[nt][0] = __expf(fmaf(SP[nt][0], C1, -mn0)); rs0 += SP[nt][0];
            SP[nt][1] = __expf(fmaf(SP[nt][1], C1, -mn0)); rs0 += SP[nt][1];
            SP[nt][2] = __expf(fmaf(SP[nt][2], C1, -mn1)); rs1 += SP[nt][2];
            SP[nt][3] = __expf(fmaf(SP[nt][3], C1, -mn1)); rs1 += SP[nt][3];
        }
        rs0 += __shfl_xor_sync(0xffffffffu, rs0, 1);
        rs0 += __shfl_xor_sync(0xffffffffu, rs0, 2);
        rs1 += __shfl_xor_sync(0xffffffffu, rs1, 1);
        rs1 += __shfl_xor_sync(0xffffffffu, rs1, 2);
        lrow0 = lrow0 * cor0 + rs0;
        lrow1 = lrow1 * cor1 + rs1;
        #pragma unroll
        for (int nt = 0; nt < 8; nt++) {
            Oa[nt][0] *= cor0; Oa[nt][1] *= cor0;
            Oa[nt][2] *= cor1; Oa[nt][3] *= cor1;
        }

        // ---- O += P V (single-term fp16 P) ----
        #pragma unroll
        for (int kk = 0; kk < 4; kk++) {
            unsigned ap[4];
            ap[0] = pk2(SP[2 * kk][0],     SP[2 * kk][1]);
            ap[1] = pk2(SP[2 * kk][2],     SP[2 * kk][3]);
            ap[2] = pk2(SP[2 * kk + 1][0], SP[2 * kk + 1][1]);
            ap[3] = pk2(SP[2 * kk + 1][2], SP[2 * kk + 1][3]);
            #pragma unroll
            for (int ntp = 0; ntp < 4; ntp++) {
                const int vrow = kk * 16 + (li & 1) * 8 + lj;
                const int vcol = ntp * 16 + (li >> 1) * 8;
                unsigned bh[4];
                LDSM4T(bh, saddr(&Vs[vrow * AP + vcol]));
                MMA_F16(Oa[2 * ntp],     ap, bh[0], bh[1]);
                MMA_F16(Oa[2 * ntp + 1], ap, bh[2], bh[3]);
            }
        }
        __syncthreads();
    }

    // ---- epilogue: normalize, split-store ctx ----
    const float il0 = 1.f / lrow0;
    const float il1 = 1.f / lrow1;
    const int r0 = qBase + m0 + g;
    #pragma unroll
    for (int nt = 0; nt < 8; nt++) {
        const int c = hoff + nt * 8 + 2 * t;
        store_split_h(Ch, Cl, (size_t)r0 * DMODEL + c,       Oa[nt][0] * il0, Oa[nt][1] * il0);
        store_split_h(Ch, Cl, (size_t)(r0 + 8) * DMODEL + c, Oa[nt][2] * il1, Oa[nt][3] * il1);
    }
}

// ---------------------------------------------------------------------------
extern "C" void kernel_launch(void* const* d_in, const int* in_sizes, int n_in,
                              void* d_out, int out_size)
{
    const float* q  = (const float*)d_in[0];
    const float* k  = (const float*)d_in[1];
    const float* v  = (const float*)d_in[2];
    const float* Wq = (const float*)d_in[3];
    const float* bq = (const float*)d_in[4];
    const float* Wk = (const float*)d_in[5];
    const float* bk = (const float*)d_in[6];
    const float* Wv = (const float*)d_in[7];
    const float* bv = (const float*)d_in[8];
    const float* Wo = (const float*)d_in[9];
    const float* bo = (const float*)d_in[10];
    float* out = (float*)d_out;

    h16* B;
    cudaGetSymbolAddress((void**)&B, g_buf);
    h16* Qf = B;
    h16* Kf = B + SDe;
    h16* Vf = B + 2 * SDe;
    h16* Ch = B + 3 * SDe;
    h16* Cl = B + 4 * SDe;

    cudaFuncSetAttribute(proj_qkv, cudaFuncAttributeMaxDynamicSharedMemorySize, 24576);
    cudaFuncSetAttribute(proj_out, cudaFuncAttributeMaxDynamicSharedMemorySize, 49152);
    cudaFuncSetAttribute(attn_f16, cudaFuncAttributeMaxDynamicSharedMemorySize, 36864);

    // fused QKV projections (read fp32 directly, convert in staging)
    dim3 gp(DMODEL / 128, S_LEN / 128, 3);
    proj_qkv<<<gp, 256, 24576>>>(q, k, v, Wq, Wk, Wv, bq, bk, bv, Qf, Kf, Vf);

    // attention
    dim3 ga(S_LEN / 128, NHEAD, 1);
    attn_f16<<<ga, 256, 36864>>>(Qf, Kf, Vf, Ch, Cl);

    // output projection (3-term split, Wo converted in staging, fp32 out)
    dim3 go(DMODEL / 128, S_LEN / 128, 1);
    proj_out<<<go, 256, 49152>>>(Ch, Cl, Wo, bo, out);
}